// round 1
// baseline (speedup 1.0000x reference)
#include <cuda_runtime.h>
#include <math.h>

// Problem dims (fixed by the dataset)
static constexpr int DIM_N = 4096;  // samples
static constexpr int DIM_D = 512;   // feature dim
static constexpr int DIM_M = 4096;  // M columns
static constexpr int DIM_K = 2048;  // centroids

// Scratch (device globals — allocation-free per harness rules)
__device__ float g_S[DIM_D * DIM_D];    // S = X^T X              [512, 512]
__device__ float g_U[DIM_K * DIM_D];    // U = C @ S              [2048, 512]
__device__ float g_T[DIM_D * DIM_M];    // T = S @ M              [512, 4096]
__device__ float g_xm2[DIM_M];          // xm2[m] = m^T S m
__device__ float g_xc2[DIM_K];          // xc2[k] = c_k^T S c_k

// ---------------------------------------------------------------------------
// 128x128x8 fp32 SGEMM, 256 threads, 8x8 accumulators per thread.
// ATRANS: A is physically [Kdim, Mdim] row-major and used as A^T (for S = X^T X).
// FUSED:  epilogue computes sqrt(max(colAdd[col] - 2*acc + rowAdd[row], 0)).
// All dims assumed multiples of the tile (true for this problem).
// ---------------------------------------------------------------------------
template <bool ATRANS, bool FUSED>
__global__ __launch_bounds__(256, 2)
void sgemm128(const float* __restrict__ A, const float* __restrict__ B,
              float* __restrict__ C,
              int Mdim, int Ndim, int Kdim,
              const float* __restrict__ rowAdd, const float* __restrict__ colAdd)
{
    __shared__ float As[8][128];
    __shared__ float Bs[8][128];

    const int tid = threadIdx.x;
    const int bx = blockIdx.x;   // N tile
    const int by = blockIdx.y;   // M tile
    const int tx = tid & 15;     // 0..15 -> 8 cols each
    const int ty = tid >> 4;     // 0..15 -> 8 rows each

    // A-load mapping (non-trans): 128 rows x 8 k, one float4 per thread
    const int a_row = tid >> 1;
    const int a_col = (tid & 1) << 2;
    // A-load mapping (trans) and B-load: 8 k x 128 cols, one float4 per thread
    const int t_row = tid >> 5;
    const int t_col = (tid & 31) << 2;

    const float* Aptr;
    if (ATRANS) Aptr = A + t_row * Mdim + by * 128 + t_col;     // A phys [Kdim, Mdim]
    else        Aptr = A + (by * 128 + a_row) * Kdim + a_col;   // A phys [Mdim, Kdim]
    const float* Bptr = B + t_row * Ndim + bx * 128 + t_col;

    float acc[8][8];
#pragma unroll
    for (int i = 0; i < 8; i++)
#pragma unroll
        for (int j = 0; j < 8; j++) acc[i][j] = 0.0f;

    for (int k0 = 0; k0 < Kdim; k0 += 8) {
        const float4 av = *(const float4*)Aptr;
        const float4 bv = *(const float4*)Bptr;
        __syncthreads();  // previous tile fully consumed before overwrite
        if (ATRANS) {
            *(float4*)&As[t_row][t_col] = av;
        } else {
            As[a_col + 0][a_row] = av.x;
            As[a_col + 1][a_row] = av.y;
            As[a_col + 2][a_row] = av.z;
            As[a_col + 3][a_row] = av.w;
        }
        *(float4*)&Bs[t_row][t_col] = bv;
        __syncthreads();

#pragma unroll
        for (int kk = 0; kk < 8; kk++) {
            float a[8], b[8];
            *(float4*)&a[0] = *(const float4*)&As[kk][ty * 8];
            *(float4*)&a[4] = *(const float4*)&As[kk][ty * 8 + 4];
            *(float4*)&b[0] = *(const float4*)&Bs[kk][tx * 8];
            *(float4*)&b[4] = *(const float4*)&Bs[kk][tx * 8 + 4];
#pragma unroll
            for (int i = 0; i < 8; i++)
#pragma unroll
                for (int j = 0; j < 8; j++)
                    acc[i][j] = fmaf(a[i], b[j], acc[i][j]);
        }

        Aptr += ATRANS ? 8 * Mdim : 8;
        Bptr += 8 * Ndim;
    }

#pragma unroll
    for (int i = 0; i < 8; i++) {
        const int row = by * 128 + ty * 8 + i;
        float radd = 0.0f;
        if (FUSED) radd = rowAdd[row];
#pragma unroll
        for (int j = 0; j < 8; j += 4) {
            const int col = bx * 128 + tx * 8 + j;
            float4 v;
            v.x = acc[i][j + 0];
            v.y = acc[i][j + 1];
            v.z = acc[i][j + 2];
            v.w = acc[i][j + 3];
            if (FUSED) {
                v.x = sqrtf(fmaxf(colAdd[col + 0] - 2.0f * v.x + radd, 0.0f));
                v.y = sqrtf(fmaxf(colAdd[col + 1] - 2.0f * v.y + radd, 0.0f));
                v.z = sqrtf(fmaxf(colAdd[col + 2] - 2.0f * v.z + radd, 0.0f));
                v.w = sqrtf(fmaxf(colAdd[col + 3] - 2.0f * v.w + radd, 0.0f));
            }
            *(float4*)&C[(size_t)row * Ndim + col] = v;
        }
    }
}

// xm2[m] = sum_d M[d,m] * T[d,m]   (column dot; coalesced across threads)
__global__ void col_dot_kernel(const float* __restrict__ Mmat,
                               const float* __restrict__ Tmat,
                               float* __restrict__ out, int rows, int cols)
{
    const int m = blockIdx.x * blockDim.x + threadIdx.x;
    if (m >= cols) return;
    float acc = 0.0f;
    for (int d = 0; d < rows; d++)
        acc = fmaf(Mmat[(size_t)d * cols + m], Tmat[(size_t)d * cols + m], acc);
    out[m] = acc;
}

// xc2[k] = sum_d C[k,d] * U[k,d]   (row dot; one warp per row)
__global__ void row_dot_kernel(const float* __restrict__ A,
                               const float* __restrict__ B,
                               float* __restrict__ out, int rows, int cols)
{
    const int warps_per_block = blockDim.x >> 5;
    const int row = blockIdx.x * warps_per_block + (threadIdx.x >> 5);
    const int lane = threadIdx.x & 31;
    if (row >= rows) return;
    float acc = 0.0f;
    for (int c = lane; c < cols; c += 32)
        acc = fmaf(A[(size_t)row * cols + c], B[(size_t)row * cols + c], acc);
#pragma unroll
    for (int o = 16; o > 0; o >>= 1)
        acc += __shfl_xor_sync(0xFFFFFFFFu, acc, o);
    if (lane == 0) out[row] = acc;
}

extern "C" void kernel_launch(void* const* d_in, const int* in_sizes, int n_in,
                              void* d_out, int out_size)
{
    const float* X = (const float*)d_in[0];  // [4096, 512]
    const float* M = (const float*)d_in[1];  // [512, 4096]
    const float* C = (const float*)d_in[2];  // [2048, 512]
    float* out = (float*)d_out;              // [2048, 4096]

    float *S, *U, *T, *xm2, *xc2;
    cudaGetSymbolAddress((void**)&S,   g_S);
    cudaGetSymbolAddress((void**)&U,   g_U);
    cudaGetSymbolAddress((void**)&T,   g_T);
    cudaGetSymbolAddress((void**)&xm2, g_xm2);
    cudaGetSymbolAddress((void**)&xc2, g_xc2);

    // 1) S = X^T X   [512,512], K=4096
    sgemm128<true, false><<<dim3(DIM_D / 128, DIM_D / 128), 256>>>(
        X, X, S, DIM_D, DIM_D, DIM_N, nullptr, nullptr);

    // 2) U = C @ S   [2048,512], K=512
    sgemm128<false, false><<<dim3(DIM_D / 128, DIM_K / 128), 256>>>(
        C, S, U, DIM_K, DIM_D, DIM_D, nullptr, nullptr);

    // 3) T = S @ M   [512,4096], K=512
    sgemm128<false, false><<<dim3(DIM_M / 128, DIM_D / 128), 256>>>(
        S, M, T, DIM_D, DIM_M, DIM_D, nullptr, nullptr);

    // 4) xm2[m] = sum_d M[d,m]*T[d,m];  xc2[k] = sum_d C[k,d]*U[k,d]
    col_dot_kernel<<<DIM_M / 256, 256>>>(M, T, xm2, DIM_D, DIM_M);
    row_dot_kernel<<<DIM_K / 8, 256>>>(C, U, xc2, DIM_K, DIM_D);

    // 5) out[k,m] = sqrt(max(xm2[m] - 2*(U@M)[k,m] + xc2[k], 0))
    sgemm128<false, true><<<dim3(DIM_M / 128, DIM_K / 128), 256>>>(
        U, M, out, DIM_K, DIM_M, DIM_D, xc2, xm2);
}

// round 4
// speedup vs baseline: 4.0510x; 4.0510x over previous
#include <cuda_runtime.h>
#include <cuda_bf16.h>
#include <cstdint>
#include <math.h>

// Problem dims (fixed)
static constexpr int DIM_N = 4096;  // samples
static constexpr int DIM_D = 512;   // feature dim
static constexpr int DIM_M = 4096;  // M columns
static constexpr int DIM_K = 2048;  // centroids
static constexpr int ZSPLIT = 8;    // split-K factor for S = X^T X

// ---------------- scratch (device globals; allocation-free) ----------------
__device__ __nv_bfloat16 g_Xt_hi[DIM_D * DIM_N];   // X^T  [512, 4096]
__device__ __nv_bfloat16 g_Xt_lo[DIM_D * DIM_N];
__device__ __nv_bfloat16 g_Mt_hi[DIM_M * DIM_D];   // M^T  [4096, 512]
__device__ __nv_bfloat16 g_Mt_lo[DIM_M * DIM_D];
__device__ __nv_bfloat16 g_C_hi[DIM_K * DIM_D];    // C    [2048, 512]
__device__ __nv_bfloat16 g_C_lo[DIM_K * DIM_D];
__device__ __nv_bfloat16 g_S_hi[DIM_D * DIM_D];    // S    [512, 512]
__device__ __nv_bfloat16 g_S_lo[DIM_D * DIM_D];
__device__ __nv_bfloat16 g_U_hi[DIM_K * DIM_D];    // U    [2048, 512]
__device__ __nv_bfloat16 g_U_lo[DIM_K * DIM_D];
__device__ float g_Spart[ZSPLIT * DIM_D * DIM_D];  // split-K partials
__device__ float g_S [DIM_D * DIM_D];
__device__ float g_U [DIM_K * DIM_D];
__device__ float g_Tt[DIM_M * DIM_D];              // (S@M)^T  [4096, 512]
__device__ float g_xm2[DIM_M];
__device__ float g_xc2[DIM_K];

// ---------------------------- warp-MMA helpers ------------------------------
__device__ __forceinline__ uint32_t smem_u32(const void* p) {
    uint32_t a;
    asm("{ .reg .u64 t; cvta.to.shared.u64 t, %1; cvt.u32.u64 %0, t; }" : "=r"(a) : "l"(p));
    return a;
}

__device__ __forceinline__ void ldm_x4(uint32_t* r, uint32_t addr) {
    asm volatile("ldmatrix.sync.aligned.m8n8.x4.shared.b16 {%0,%1,%2,%3}, [%4];"
                 : "=r"(r[0]), "=r"(r[1]), "=r"(r[2]), "=r"(r[3]) : "r"(addr));
}
__device__ __forceinline__ void ldm_x2(uint32_t* r, uint32_t addr) {
    asm volatile("ldmatrix.sync.aligned.m8n8.x2.shared.b16 {%0,%1}, [%2];"
                 : "=r"(r[0]), "=r"(r[1]) : "r"(addr));
}
__device__ __forceinline__ void mma_bf16(float* c, const uint32_t* a, const uint32_t* b) {
    asm volatile("mma.sync.aligned.m16n8k16.row.col.f32.bf16.bf16.f32 "
                 "{%0,%1,%2,%3}, {%4,%5,%6,%7}, {%8,%9}, {%0,%1,%2,%3};"
                 : "+f"(c[0]), "+f"(c[1]), "+f"(c[2]), "+f"(c[3])
                 : "r"(a[0]), "r"(a[1]), "r"(a[2]), "r"(a[3]), "r"(b[0]), "r"(b[1]));
}

// ---------------------------------------------------------------------------
// Split-bf16 GEMM via mma.sync:  C[i,j] = sum_k (Ahi+Alo)[i,k] * (Bhi+Blo)[j,k]
// (drops lo*lo; rel err ~2^-18). A [Mo,Ktot] K-major, B [No,Ktot] K-major.
// CTA tile 128x128, K-slab 32, 256 threads = 8 warps (2x4), warp tile 64x32.
// smem row stride 80B (5 x 16B granules; gcd(5,8)=1 -> ldmatrix conflict-free).
// grid = (No/128, Mo/128, zsplits); z slice: kbase = z*kspan, out += z*zstride.
// FUSED: out = sqrt(max(colAdd[col] - 2*acc + rowAdd[row], 0)).
// ---------------------------------------------------------------------------
static constexpr int RSTRIDE = 80;                  // padded smem row stride (bytes)
static constexpr int TILE_BYTES_PAD = 128 * RSTRIDE;

template <bool FUSED>
__global__ __launch_bounds__(256, 2)
void bf16s_gemm(const __nv_bfloat16* __restrict__ Ahi, const __nv_bfloat16* __restrict__ Alo,
                const __nv_bfloat16* __restrict__ Bhi, const __nv_bfloat16* __restrict__ Blo,
                float* __restrict__ Cout,
                int No, int Ktot, int kspan, size_t zstride,
                const float* __restrict__ rowAdd, const float* __restrict__ colAdd)
{
    __shared__ __align__(16) unsigned char smem[4 * TILE_BYTES_PAD];
    const uint32_t sbase = smem_u32(smem);
    const uint32_t OFF_AHI = 0, OFF_ALO = TILE_BYTES_PAD,
                   OFF_BHI = 2 * TILE_BYTES_PAD, OFF_BLO = 3 * TILE_BYTES_PAD;

    const int tid = threadIdx.x;
    const int wid = tid >> 5;
    const int lane = tid & 31;
    const int warp_m = wid >> 2;     // 0..1 -> 64 rows each
    const int warp_n = wid & 3;      // 0..3 -> 32 cols each
    const int rowA0 = blockIdx.y * 128;
    const int rowB0 = blockIdx.x * 128;
    const int kz = blockIdx.z * kspan;
    const int nslabs = kspan / 32;
    Cout += (size_t)blockIdx.z * zstride;

    float acc[4][4][4];
#pragma unroll
    for (int i = 0; i < 4; i++)
#pragma unroll
        for (int j = 0; j < 4; j++)
#pragma unroll
            for (int v = 0; v < 4; v++) acc[i][j][v] = 0.0f;

    // ldmatrix source addresses (lane-dependent, k-invariant parts)
    // A frags: row = warp_m*64 + mi*16 + (lane&15), 16B chunk = lane>>4 within k16
    const int a_row = warp_m * 64 + (lane & 15);
    const uint32_t a_coff = (uint32_t)((lane >> 4) << 4);
    // B frags: row = warp_n*32 + nj*8 + (lane&7), chunk = (lane>>3)&1
    const int b_row = warp_n * 32 + (lane & 7);
    const uint32_t b_coff = (uint32_t)(((lane >> 3) & 1) << 4);

    for (int slab = 0; slab < nslabs; slab++) {
        const int kbase = kz + slab * 32;
        __syncthreads();   // previous slab fully consumed
        // Load 4 tiles of [128 x 32 bf16]: 512 16B chunks each, 2 per thread.
#pragma unroll
        for (int i = 0; i < 2; i++) {
            const int idx = tid + i * 256;       // 0..511
            const int r = idx >> 2;
            const int c = idx & 3;
            const size_t aoff = (size_t)(rowA0 + r) * Ktot + kbase + c * 8;
            const size_t boff = (size_t)(rowB0 + r) * Ktot + kbase + c * 8;
            const uint32_t so = (uint32_t)(r * RSTRIDE + c * 16);
            *(uint4*)(smem + OFF_AHI + so) = *(const uint4*)(Ahi + aoff);
            *(uint4*)(smem + OFF_ALO + so) = *(const uint4*)(Alo + aoff);
            *(uint4*)(smem + OFF_BHI + so) = *(const uint4*)(Bhi + boff);
            *(uint4*)(smem + OFF_BLO + so) = *(const uint4*)(Blo + boff);
        }
        __syncthreads();

#pragma unroll
        for (int kk = 0; kk < 2; kk++) {         // two k16 steps per slab
            const uint32_t kcol = kk * 32;
            uint32_t a_hi[4][4], a_lo[4][4], b_hi[4][2], b_lo[4][2];
#pragma unroll
            for (int mi = 0; mi < 4; mi++) {
                const uint32_t ar = (uint32_t)((a_row + mi * 16) * RSTRIDE) + kcol + a_coff;
                ldm_x4(a_hi[mi], sbase + OFF_AHI + ar);
                ldm_x4(a_lo[mi], sbase + OFF_ALO + ar);
            }
#pragma unroll
            for (int nj = 0; nj < 4; nj++) {
                const uint32_t br = (uint32_t)((b_row + nj * 8) * RSTRIDE) + kcol + b_coff;
                ldm_x2(b_hi[nj], sbase + OFF_BHI + br);
                ldm_x2(b_lo[nj], sbase + OFF_BLO + br);
            }
#pragma unroll
            for (int mi = 0; mi < 4; mi++)
#pragma unroll
                for (int nj = 0; nj < 4; nj++) {
                    mma_bf16(acc[mi][nj], a_hi[mi], b_hi[nj]);
                    mma_bf16(acc[mi][nj], a_hi[mi], b_lo[nj]);
                    mma_bf16(acc[mi][nj], a_lo[mi], b_hi[nj]);
                }
        }
    }

    // Epilogue. c-frag layout: c0,c1 -> row lane/4,   cols (lane%4)*2 + {0,1}
    //                          c2,c3 -> row lane/4+8, same cols
    const int er0 = rowA0 + warp_m * 64 + (lane >> 2);
    const int ec0 = rowB0 + warp_n * 32 + (lane & 3) * 2;
#pragma unroll
    for (int mi = 0; mi < 4; mi++) {
#pragma unroll
        for (int half = 0; half < 2; half++) {
            const int row = er0 + mi * 16 + half * 8;
            float radd = 0.0f;
            if (FUSED) radd = rowAdd[row];
#pragma unroll
            for (int nj = 0; nj < 4; nj++) {
                const int col = ec0 + nj * 8;
                float2 v;
                v.x = acc[mi][nj][half * 2 + 0];
                v.y = acc[mi][nj][half * 2 + 1];
                if (FUSED) {
                    const float2 ca = *(const float2*)(colAdd + col);
                    v.x = sqrtf(fmaxf(ca.x - 2.0f * v.x + radd, 0.0f));
                    v.y = sqrtf(fmaxf(ca.y - 2.0f * v.y + radd, 0.0f));
                }
                *(float2*)(Cout + (size_t)row * No + col) = v;
            }
        }
    }
}

// ------------------------- conversion / small kernels -----------------------
__global__ void split_kernel(const float* __restrict__ in,
                             __nv_bfloat16* __restrict__ hi,
                             __nv_bfloat16* __restrict__ lo, int n)
{
    const int i = blockIdx.x * blockDim.x + threadIdx.x;
    if (i >= n) return;
    const float x = in[i];
    const __nv_bfloat16 h = __float2bfloat16_rn(x);
    hi[i] = h;
    lo[i] = __float2bfloat16_rn(x - __bfloat162float(h));
}

// in [R,C] fp32 -> hi/lo [C,R] bf16 (transpose)
__global__ void split_transpose_kernel(const float* __restrict__ in,
                                       __nv_bfloat16* __restrict__ hi,
                                       __nv_bfloat16* __restrict__ lo, int R, int C)
{
    __shared__ float t[32][33];
    const int x = blockIdx.x * 32 + threadIdx.x;  // col in input
    const int y0 = blockIdx.y * 32;
#pragma unroll
    for (int j = 0; j < 32; j += 8)
        t[threadIdx.y + j][threadIdx.x] = in[(size_t)(y0 + threadIdx.y + j) * C + x];
    __syncthreads();
#pragma unroll
    for (int j = 0; j < 32; j += 8) {
        const int c = blockIdx.x * 32 + threadIdx.y + j;  // out row (= input col)
        const int r = y0 + threadIdx.x;                   // out col (= input row)
        const float v = t[threadIdx.x][threadIdx.y + j];
        const __nv_bfloat16 h = __float2bfloat16_rn(v);
        hi[(size_t)c * R + r] = h;
        lo[(size_t)c * R + r] = __float2bfloat16_rn(v - __bfloat162float(h));
    }
}

__global__ void reduce_z_kernel(const float* __restrict__ part, float* __restrict__ out, int n)
{
    const int i = blockIdx.x * blockDim.x + threadIdx.x;
    if (i >= n) return;
    float acc = 0.0f;
#pragma unroll
    for (int z = 0; z < ZSPLIT; z++) acc += part[i + (size_t)z * n];
    out[i] = acc;
}

// xc2[k] = sum_d A[k,d]*B[k,d]  (fp32 x fp32, one warp per row)
__global__ void row_dot_kernel(const float* __restrict__ A, const float* __restrict__ B,
                               float* __restrict__ out, int rows, int cols)
{
    const int row = blockIdx.x * (blockDim.x >> 5) + (threadIdx.x >> 5);
    const int lane = threadIdx.x & 31;
    if (row >= rows) return;
    float acc = 0.0f;
    for (int c = lane; c < cols; c += 32)
        acc = fmaf(A[(size_t)row * cols + c], B[(size_t)row * cols + c], acc);
#pragma unroll
    for (int o = 16; o > 0; o >>= 1) acc += __shfl_xor_sync(0xFFFFFFFFu, acc, o);
    if (lane == 0) out[row] = acc;
}

// xm2[m] = sum_d (Mt_hi+Mt_lo)[m,d] * Tt[m,d]
__global__ void row_dot_split_kernel(const __nv_bfloat16* __restrict__ Ahi,
                                     const __nv_bfloat16* __restrict__ Alo,
                                     const float* __restrict__ B,
                                     float* __restrict__ out, int rows, int cols)
{
    const int row = blockIdx.x * (blockDim.x >> 5) + (threadIdx.x >> 5);
    const int lane = threadIdx.x & 31;
    if (row >= rows) return;
    float acc = 0.0f;
    for (int c = lane; c < cols; c += 32) {
        const size_t o = (size_t)row * cols + c;
        const float a = __bfloat162float(Ahi[o]) + __bfloat162float(Alo[o]);
        acc = fmaf(a, B[o], acc);
    }
#pragma unroll
    for (int o = 16; o > 0; o >>= 1) acc += __shfl_xor_sync(0xFFFFFFFFu, acc, o);
    if (lane == 0) out[row] = acc;
}

// --------------------------------- launch ----------------------------------
extern "C" void kernel_launch(void* const* d_in, const int* in_sizes, int n_in,
                              void* d_out, int out_size)
{
    const float* X = (const float*)d_in[0];  // [4096, 512]
    const float* M = (const float*)d_in[1];  // [512, 4096]
    const float* C = (const float*)d_in[2];  // [2048, 512]
    float* out = (float*)d_out;              // [2048, 4096]

    __nv_bfloat16 *Xt_hi, *Xt_lo, *Mt_hi, *Mt_lo, *C_hi, *C_lo, *S_hi, *S_lo, *U_hi, *U_lo;
    float *Spart, *S, *U, *Tt, *xm2, *xc2;
    cudaGetSymbolAddress((void**)&Xt_hi, g_Xt_hi);
    cudaGetSymbolAddress((void**)&Xt_lo, g_Xt_lo);
    cudaGetSymbolAddress((void**)&Mt_hi, g_Mt_hi);
    cudaGetSymbolAddress((void**)&Mt_lo, g_Mt_lo);
    cudaGetSymbolAddress((void**)&C_hi,  g_C_hi);
    cudaGetSymbolAddress((void**)&C_lo,  g_C_lo);
    cudaGetSymbolAddress((void**)&S_hi,  g_S_hi);
    cudaGetSymbolAddress((void**)&S_lo,  g_S_lo);
    cudaGetSymbolAddress((void**)&U_hi,  g_U_hi);
    cudaGetSymbolAddress((void**)&U_lo,  g_U_lo);
    cudaGetSymbolAddress((void**)&Spart, g_Spart);
    cudaGetSymbolAddress((void**)&S,     g_S);
    cudaGetSymbolAddress((void**)&U,     g_U);
    cudaGetSymbolAddress((void**)&Tt,    g_Tt);
    cudaGetSymbolAddress((void**)&xm2,   g_xm2);
    cudaGetSymbolAddress((void**)&xc2,   g_xc2);

    // 1) transposed splits:  Xt [512,4096], Mt [4096,512]
    split_transpose_kernel<<<dim3(DIM_D / 32, DIM_N / 32), dim3(32, 8)>>>(X, Xt_hi, Xt_lo, DIM_N, DIM_D);
    split_transpose_kernel<<<dim3(DIM_M / 32, DIM_D / 32), dim3(32, 8)>>>(M, Mt_hi, Mt_lo, DIM_D, DIM_M);
    split_kernel<<<(DIM_K * DIM_D) / 256, 256>>>(C, C_hi, C_lo, DIM_K * DIM_D);

    // 2) S = Xt @ Xt^T  [512,512], K=4096, split-K=8
    bf16s_gemm<false><<<dim3(DIM_D / 128, DIM_D / 128, ZSPLIT), 256>>>(
        Xt_hi, Xt_lo, Xt_hi, Xt_lo, Spart,
        DIM_D, DIM_N, DIM_N / ZSPLIT, (size_t)DIM_D * DIM_D, nullptr, nullptr);
    reduce_z_kernel<<<(DIM_D * DIM_D) / 256, 256>>>(Spart, S, DIM_D * DIM_D);
    split_kernel<<<(DIM_D * DIM_D) / 256, 256>>>(S, S_hi, S_lo, DIM_D * DIM_D);

    // 3) U = C @ S  [2048,512] (S symmetric -> S rows are a valid K-major B)
    bf16s_gemm<false><<<dim3(DIM_D / 128, DIM_K / 128, 1), 256>>>(
        C_hi, C_lo, S_hi, S_lo, U, DIM_D, DIM_D, DIM_D, 0, nullptr, nullptr);
    split_kernel<<<(DIM_K * DIM_D) / 256, 256>>>(U, U_hi, U_lo, DIM_K * DIM_D);

    // 4) Tt = (S @ M)^T = Mt @ S  [4096,512]
    bf16s_gemm<false><<<dim3(DIM_D / 128, DIM_M / 128, 1), 256>>>(
        Mt_hi, Mt_lo, S_hi, S_lo, Tt, DIM_D, DIM_D, DIM_D, 0, nullptr, nullptr);

    // 5) xm2[m] = m^T S m ; xc2[k] = c_k^T S c_k
    row_dot_split_kernel<<<DIM_M / 8, 256>>>(Mt_hi, Mt_lo, Tt, xm2, DIM_M, DIM_D);
    row_dot_kernel<<<DIM_K / 8, 256>>>(C, U, xc2, DIM_K, DIM_D);

    // 6) out[k,m] = sqrt(max(xm2[m] - 2*(U @ Mt^T)[k,m] + xc2[k], 0))
    bf16s_gemm<true><<<dim3(DIM_M / 128, DIM_K / 128, 1), 256>>>(
        U_hi, U_lo, Mt_hi, Mt_lo, out, DIM_M, DIM_D, DIM_D, 0, xc2, xm2);
}

// round 5
// speedup vs baseline: 4.6001x; 1.1355x over previous
#include <cuda_runtime.h>
#include <cuda_bf16.h>
#include <cstdint>
#include <math.h>

// Problem dims (fixed)
static constexpr int DIM_N = 4096;  // samples
static constexpr int DIM_D = 512;   // feature dim
static constexpr int DIM_M = 4096;  // M columns
static constexpr int DIM_K = 2048;  // centroids
static constexpr int ZSPLIT = 16;   // split-K factor for S = X^T X

// ---------------- scratch (device globals; allocation-free) ----------------
__device__ __nv_bfloat16 g_Xt_hi[DIM_D * DIM_N];   // X^T  [512, 4096]
__device__ __nv_bfloat16 g_Xt_lo[DIM_D * DIM_N];
__device__ __nv_bfloat16 g_Mt_hi[DIM_M * DIM_D];   // M^T  [4096, 512]
__device__ __nv_bfloat16 g_Mt_lo[DIM_M * DIM_D];
__device__ __nv_bfloat16 g_C_hi[DIM_K * DIM_D];    // C    [2048, 512]
__device__ __nv_bfloat16 g_C_lo[DIM_K * DIM_D];
__device__ __nv_bfloat16 g_S_hi[DIM_D * DIM_D];    // S    [512, 512]
__device__ __nv_bfloat16 g_S_lo[DIM_D * DIM_D];
__device__ __nv_bfloat16 g_U_hi[DIM_K * DIM_D];    // U    [2048, 512]
__device__ __nv_bfloat16 g_U_lo[DIM_K * DIM_D];
__device__ float g_Spart[ZSPLIT * DIM_D * DIM_D];  // split-K partials
__device__ float g_S [DIM_D * DIM_D];
__device__ float g_U [DIM_K * DIM_D];
__device__ float g_Tt[DIM_M * DIM_D];              // (S@M)^T  [4096, 512]
__device__ float g_xm2[DIM_M];
__device__ float g_xc2[DIM_K];

// ---------------------------- warp-MMA helpers ------------------------------
__device__ __forceinline__ uint32_t smem_u32(const void* p) {
    uint32_t a;
    asm("{ .reg .u64 t; cvta.to.shared.u64 t, %1; cvt.u32.u64 %0, t; }" : "=r"(a) : "l"(p));
    return a;
}
__device__ __forceinline__ void ldm_x4(uint32_t* r, uint32_t addr) {
    asm volatile("ldmatrix.sync.aligned.m8n8.x4.shared.b16 {%0,%1,%2,%3}, [%4];"
                 : "=r"(r[0]), "=r"(r[1]), "=r"(r[2]), "=r"(r[3]) : "r"(addr));
}
__device__ __forceinline__ void mma_bf16(float* c, const uint32_t* a, const uint32_t* b) {
    asm volatile("mma.sync.aligned.m16n8k16.row.col.f32.bf16.bf16.f32 "
                 "{%0,%1,%2,%3}, {%4,%5,%6,%7}, {%8,%9}, {%0,%1,%2,%3};"
                 : "+f"(c[0]), "+f"(c[1]), "+f"(c[2]), "+f"(c[3])
                 : "r"(a[0]), "r"(a[1]), "r"(a[2]), "r"(a[3]), "r"(b[0]), "r"(b[1]));
}
#define CP_ASYNC16(dst, src) \
    asm volatile("cp.async.cg.shared.global [%0], [%1], 16;" :: "r"(dst), "l"(src))
#define CP_COMMIT() asm volatile("cp.async.commit_group;" ::: "memory")
#define CP_WAIT1()  asm volatile("cp.async.wait_group 1;" ::: "memory")
#define CP_WAIT0()  asm volatile("cp.async.wait_group 0;" ::: "memory")

// ---------------------------------------------------------------------------
// Split-bf16 GEMM via mma.sync:  C[i,j] = sum_k (Ahi+Alo)[i,k] * (Bhi+Blo)[j,k]
// (drops lo*lo; rel err ~2^-18). A [Mo,Ktot] K-major, B [No,Ktot] K-major.
// CTA tile 128x128, K-slab 32, 256 threads = 8 warps (2x4), warp tile 64x32.
// cp.async double-buffered (2 stages x 40KB dynamic smem).
// smem row stride 80B (5 x 16B granules; gcd(5,8)=1 -> ldmatrix conflict-free).
// grid = (No/128, Mo/128, zsplits); z slice: kbase = z*kspan, out += z*zstride.
// FUSED: out = sqrt(max(colAdd[col] - 2*acc + rowAdd[row], 0)).
// ---------------------------------------------------------------------------
static constexpr int RSTRIDE = 80;                   // padded smem row stride (bytes)
static constexpr int TILE_BYTES_PAD = 128 * RSTRIDE; // 10240
static constexpr int STAGE_BYTES = 4 * TILE_BYTES_PAD; // 40960
static constexpr int GEMM_SMEM = 2 * STAGE_BYTES;    // 81920

template <bool FUSED>
__global__ __launch_bounds__(256, 2)
void bf16s_gemm(const __nv_bfloat16* __restrict__ Ahi, const __nv_bfloat16* __restrict__ Alo,
                const __nv_bfloat16* __restrict__ Bhi, const __nv_bfloat16* __restrict__ Blo,
                float* __restrict__ Cout,
                int No, int Ktot, int kspan, size_t zstride,
                const float* __restrict__ rowAdd, const float* __restrict__ colAdd)
{
    extern __shared__ __align__(128) unsigned char smem[];
    const uint32_t sbase = smem_u32(smem);
    const uint32_t OFF_AHI = 0, OFF_ALO = TILE_BYTES_PAD,
                   OFF_BHI = 2 * TILE_BYTES_PAD, OFF_BLO = 3 * TILE_BYTES_PAD;

    const int tid = threadIdx.x;
    const int wid = tid >> 5;
    const int lane = tid & 31;
    const int warp_m = wid >> 2;     // 0..1 -> 64 rows each
    const int warp_n = wid & 3;      // 0..3 -> 32 cols each
    const int rowA0 = blockIdx.y * 128;
    const int rowB0 = blockIdx.x * 128;
    const int kz = blockIdx.z * kspan;
    const int nslabs = kspan / 32;
    Cout += (size_t)blockIdx.z * zstride;

    float acc[4][4][4];
#pragma unroll
    for (int i = 0; i < 4; i++)
#pragma unroll
        for (int j = 0; j < 4; j++)
#pragma unroll
            for (int v = 0; v < 4; v++) acc[i][j][v] = 0.0f;

    // per-thread gmem/smem mapping for slab loads (2 x 16B per matrix)
    const int l_r0 = tid >> 1;                 // rows 0..127 (i=0)
    const int l_c0 = (tid & 1) << 1;           // chunks {0,1} or {2,3}? -> c = (tid&1)*2 + i? 
    // simpler: idx = tid + i*256; r = idx>>2; c = idx&3  (as before)

    // ldmatrix lane addressing (k-invariant parts)
    const int a_row = warp_m * 64 + (lane & 15);
    const uint32_t a_coff = (uint32_t)((lane >> 4) << 4);
    // B x4 pair: pair p covers nj=2p,2p+1. row/chunk per lane:
    const int b_row = warp_n * 32 + ((lane >> 4) << 3) + (lane & 7);
    const uint32_t b_coff = (uint32_t)(((lane >> 3) & 1) << 4);

    auto load_slab = [&](int slab, int stage) {
        const int kbase = kz + slab * 32;
        const uint32_t st = (uint32_t)stage * STAGE_BYTES;
#pragma unroll
        for (int i = 0; i < 2; i++) {
            const int idx = tid + i * 256;       // 0..511
            const int r = idx >> 2;
            const int c = idx & 3;
            const size_t aoff = (size_t)(rowA0 + r) * Ktot + kbase + c * 8;
            const size_t boff = (size_t)(rowB0 + r) * Ktot + kbase + c * 8;
            const uint32_t so = st + (uint32_t)(r * RSTRIDE + c * 16);
            CP_ASYNC16(sbase + OFF_AHI + so, Ahi + aoff);
            CP_ASYNC16(sbase + OFF_ALO + so, Alo + aoff);
            CP_ASYNC16(sbase + OFF_BHI + so, Bhi + boff);
            CP_ASYNC16(sbase + OFF_BLO + so, Blo + boff);
        }
    };

    load_slab(0, 0);
    CP_COMMIT();

    for (int slab = 0; slab < nslabs; slab++) {
        const int cur = slab & 1;
        if (slab + 1 < nslabs) {
            load_slab(slab + 1, cur ^ 1);
            CP_COMMIT();
            CP_WAIT1();
        } else {
            CP_WAIT0();
        }
        __syncthreads();          // slab data visible to all warps

        const uint32_t st = (uint32_t)cur * STAGE_BYTES;
#pragma unroll
        for (int kk = 0; kk < 2; kk++) {         // two k16 steps per slab
            const uint32_t kcol = kk * 32;
            uint32_t a_hi[4][4], a_lo[4][4], b_hi[2][4], b_lo[2][4];
#pragma unroll
            for (int mi = 0; mi < 4; mi++) {
                const uint32_t ar = st + (uint32_t)((a_row + mi * 16) * RSTRIDE) + kcol + a_coff;
                ldm_x4(a_hi[mi], sbase + OFF_AHI + ar);
                ldm_x4(a_lo[mi], sbase + OFF_ALO + ar);
            }
#pragma unroll
            for (int p = 0; p < 2; p++) {        // nj pairs {0,1}, {2,3}
                const uint32_t br = st + (uint32_t)((b_row + p * 16) * RSTRIDE) + kcol + b_coff;
                ldm_x4(b_hi[p], sbase + OFF_BHI + br);
                ldm_x4(b_lo[p], sbase + OFF_BLO + br);
            }
#pragma unroll
            for (int mi = 0; mi < 4; mi++)
#pragma unroll
                for (int nj = 0; nj < 4; nj++) {
                    const uint32_t* bh = &b_hi[nj >> 1][(nj & 1) * 2];
                    const uint32_t* bl = &b_lo[nj >> 1][(nj & 1) * 2];
                    mma_bf16(acc[mi][nj], a_hi[mi], bh);
                    mma_bf16(acc[mi][nj], a_hi[mi], bl);
                    mma_bf16(acc[mi][nj], a_lo[mi], bh);
                }
        }
        __syncthreads();          // compute done before stage is overwritten
    }

    // Epilogue. c-frag layout: c0,c1 -> row lane/4,   cols (lane%4)*2 + {0,1}
    //                          c2,c3 -> row lane/4+8, same cols
    const int er0 = rowA0 + warp_m * 64 + (lane >> 2);
    const int ec0 = rowB0 + warp_n * 32 + (lane & 3) * 2;
#pragma unroll
    for (int mi = 0; mi < 4; mi++) {
#pragma unroll
        for (int half = 0; half < 2; half++) {
            const int row = er0 + mi * 16 + half * 8;
            float radd = 0.0f;
            if (FUSED) radd = rowAdd[row];
#pragma unroll
            for (int nj = 0; nj < 4; nj++) {
                const int col = ec0 + nj * 8;
                float2 v;
                v.x = acc[mi][nj][half * 2 + 0];
                v.y = acc[mi][nj][half * 2 + 1];
                if (FUSED) {
                    const float2 ca = *(const float2*)(colAdd + col);
                    v.x = sqrtf(fmaxf(ca.x - 2.0f * v.x + radd, 0.0f));
                    v.y = sqrtf(fmaxf(ca.y - 2.0f * v.y + radd, 0.0f));
                }
                *(float2*)(Cout + (size_t)row * No + col) = v;
            }
        }
    }
}

// ------------------------- conversion / small kernels -----------------------
__global__ void split_kernel(const float* __restrict__ in,
                             __nv_bfloat16* __restrict__ hi,
                             __nv_bfloat16* __restrict__ lo, int n)
{
    const int i = blockIdx.x * blockDim.x + threadIdx.x;
    if (i >= n) return;
    const float x = in[i];
    const __nv_bfloat16 h = __float2bfloat16_rn(x);
    hi[i] = h;
    lo[i] = __float2bfloat16_rn(x - __bfloat162float(h));
}

// in [R,C] fp32 -> hi/lo [C,R] bf16 (transpose)
__global__ void split_transpose_kernel(const float* __restrict__ in,
                                       __nv_bfloat16* __restrict__ hi,
                                       __nv_bfloat16* __restrict__ lo, int R, int C)
{
    __shared__ float t[32][33];
    const int x = blockIdx.x * 32 + threadIdx.x;  // col in input
    const int y0 = blockIdx.y * 32;
#pragma unroll
    for (int j = 0; j < 32; j += 8)
        t[threadIdx.y + j][threadIdx.x] = in[(size_t)(y0 + threadIdx.y + j) * C + x];
    __syncthreads();
#pragma unroll
    for (int j = 0; j < 32; j += 8) {
        const int c = blockIdx.x * 32 + threadIdx.y + j;  // out row (= input col)
        const int r = y0 + threadIdx.x;                   // out col (= input row)
        const float v = t[threadIdx.x][threadIdx.y + j];
        const __nv_bfloat16 h = __float2bfloat16_rn(v);
        hi[(size_t)c * R + r] = h;
        lo[(size_t)c * R + r] = __float2bfloat16_rn(v - __bfloat162float(h));
    }
}

__global__ void reduce_z_kernel(const float* __restrict__ part, float* __restrict__ out, int n)
{
    const int i = blockIdx.x * blockDim.x + threadIdx.x;
    if (i >= n) return;
    float acc = 0.0f;
#pragma unroll
    for (int z = 0; z < ZSPLIT; z++) acc += part[i + (size_t)z * n];
    out[i] = acc;
}

// xc2[k] = sum_d A[k,d]*B[k,d]  (fp32 x fp32, one warp per row)
__global__ void row_dot_kernel(const float* __restrict__ A, const float* __restrict__ B,
                               float* __restrict__ out, int rows, int cols)
{
    const int row = blockIdx.x * (blockDim.x >> 5) + (threadIdx.x >> 5);
    const int lane = threadIdx.x & 31;
    if (row >= rows) return;
    float acc = 0.0f;
    for (int c = lane; c < cols; c += 32)
        acc = fmaf(A[(size_t)row * cols + c], B[(size_t)row * cols + c], acc);
#pragma unroll
    for (int o = 16; o > 0; o >>= 1) acc += __shfl_xor_sync(0xFFFFFFFFu, acc, o);
    if (lane == 0) out[row] = acc;
}

// xm2[m] = sum_d (Mt_hi+Mt_lo)[m,d] * Tt[m,d]
__global__ void row_dot_split_kernel(const __nv_bfloat16* __restrict__ Ahi,
                                     const __nv_bfloat16* __restrict__ Alo,
                                     const float* __restrict__ B,
                                     float* __restrict__ out, int rows, int cols)
{
    const int row = blockIdx.x * (blockDim.x >> 5) + (threadIdx.x >> 5);
    const int lane = threadIdx.x & 31;
    if (row >= rows) return;
    float acc = 0.0f;
    for (int c = lane; c < cols; c += 32) {
        const size_t o = (size_t)row * cols + c;
        const float a = __bfloat162float(Ahi[o]) + __bfloat162float(Alo[o]);
        acc = fmaf(a, B[o], acc);
    }
#pragma unroll
    for (int o = 16; o > 0; o >>= 1) acc += __shfl_xor_sync(0xFFFFFFFFu, acc, o);
    if (lane == 0) out[row] = acc;
}

// --------------------------------- launch ----------------------------------
extern "C" void kernel_launch(void* const* d_in, const int* in_sizes, int n_in,
                              void* d_out, int out_size)
{
    const float* X = (const float*)d_in[0];  // [4096, 512]
    const float* M = (const float*)d_in[1];  // [512, 4096]
    const float* C = (const float*)d_in[2];  // [2048, 512]
    float* out = (float*)d_out;              // [2048, 4096]

    static bool attr_done = false;
    if (!attr_done) {
        cudaFuncSetAttribute(bf16s_gemm<false>, cudaFuncAttributeMaxDynamicSharedMemorySize, GEMM_SMEM);
        cudaFuncSetAttribute(bf16s_gemm<true>,  cudaFuncAttributeMaxDynamicSharedMemorySize, GEMM_SMEM);
        attr_done = true;
    }

    __nv_bfloat16 *Xt_hi, *Xt_lo, *Mt_hi, *Mt_lo, *C_hi, *C_lo, *S_hi, *S_lo, *U_hi, *U_lo;
    float *Spart, *S, *U, *Tt, *xm2, *xc2;
    cudaGetSymbolAddress((void**)&Xt_hi, g_Xt_hi);
    cudaGetSymbolAddress((void**)&Xt_lo, g_Xt_lo);
    cudaGetSymbolAddress((void**)&Mt_hi, g_Mt_hi);
    cudaGetSymbolAddress((void**)&Mt_lo, g_Mt_lo);
    cudaGetSymbolAddress((void**)&C_hi,  g_C_hi);
    cudaGetSymbolAddress((void**)&C_lo,  g_C_lo);
    cudaGetSymbolAddress((void**)&S_hi,  g_S_hi);
    cudaGetSymbolAddress((void**)&S_lo,  g_S_lo);
    cudaGetSymbolAddress((void**)&U_hi,  g_U_hi);
    cudaGetSymbolAddress((void**)&U_lo,  g_U_lo);
    cudaGetSymbolAddress((void**)&Spart, g_Spart);
    cudaGetSymbolAddress((void**)&S,     g_S);
    cudaGetSymbolAddress((void**)&U,     g_U);
    cudaGetSymbolAddress((void**)&Tt,    g_Tt);
    cudaGetSymbolAddress((void**)&xm2,   g_xm2);
    cudaGetSymbolAddress((void**)&xc2,   g_xc2);

    // 1) transposed splits:  Xt [512,4096], Mt [4096,512]
    split_transpose_kernel<<<dim3(DIM_D / 32, DIM_N / 32), dim3(32, 8)>>>(X, Xt_hi, Xt_lo, DIM_N, DIM_D);
    split_transpose_kernel<<<dim3(DIM_M / 32, DIM_D / 32), dim3(32, 8)>>>(M, Mt_hi, Mt_lo, DIM_D, DIM_M);
    split_kernel<<<(DIM_K * DIM_D) / 256, 256>>>(C, C_hi, C_lo, DIM_K * DIM_D);

    // 2) S = Xt @ Xt^T  [512,512], K=4096, split-K=16
    bf16s_gemm<false><<<dim3(DIM_D / 128, DIM_D / 128, ZSPLIT), 256, GEMM_SMEM>>>(
        Xt_hi, Xt_lo, Xt_hi, Xt_lo, Spart,
        DIM_D, DIM_N, DIM_N / ZSPLIT, (size_t)DIM_D * DIM_D, nullptr, nullptr);
    reduce_z_kernel<<<(DIM_D * DIM_D) / 256, 256>>>(Spart, S, DIM_D * DIM_D);
    split_kernel<<<(DIM_D * DIM_D) / 256, 256>>>(S, S_hi, S_lo, DIM_D * DIM_D);

    // 3) U = C @ S  [2048,512] (S symmetric -> S rows are a valid K-major B)
    bf16s_gemm<false><<<dim3(DIM_D / 128, DIM_K / 128, 1), 256, GEMM_SMEM>>>(
        C_hi, C_lo, S_hi, S_lo, U, DIM_D, DIM_D, DIM_D, 0, nullptr, nullptr);
    split_kernel<<<(DIM_K * DIM_D) / 256, 256>>>(U, U_hi, U_lo, DIM_K * DIM_D);

    // 4) Tt = (S @ M)^T = Mt @ S  [4096,512]
    bf16s_gemm<false><<<dim3(DIM_D / 128, DIM_M / 128, 1), 256, GEMM_SMEM>>>(
        Mt_hi, Mt_lo, S_hi, S_lo, Tt, DIM_D, DIM_D, DIM_D, 0, nullptr, nullptr);

    // 5) xm2[m] = m^T S m ; xc2[k] = c_k^T S c_k
    row_dot_split_kernel<<<DIM_M / 8, 256>>>(Mt_hi, Mt_lo, Tt, xm2, DIM_M, DIM_D);
    row_dot_kernel<<<DIM_K / 8, 256>>>(C, U, xc2, DIM_K, DIM_D);

    // 6) out[k,m] = sqrt(max(xm2[m] - 2*(U @ Mt^T)[k,m] + xc2[k], 0))
    bf16s_gemm<true><<<dim3(DIM_M / 128, DIM_K / 128, 1), 256, GEMM_SMEM>>>(
        U_hi, U_lo, Mt_hi, Mt_lo, out, DIM_M, DIM_D, DIM_D, 0, xc2, xm2);
}

// round 6
// speedup vs baseline: 4.7008x; 1.0219x over previous
#include <cuda_runtime.h>
#include <cuda_bf16.h>
#include <cstdint>
#include <math.h>

// Problem dims (fixed)
static constexpr int DIM_N = 4096;  // samples
static constexpr int DIM_D = 512;   // feature dim
static constexpr int DIM_M = 4096;  // M columns
static constexpr int DIM_K = 2048;  // centroids
static constexpr int ZSPLIT = 16;   // split-K factor for S = X^T X
static constexpr int DIM_CM = DIM_K + DIM_M;  // stacked [C; Mt] rows = 6144

// ---------------- scratch (device globals; allocation-free) ----------------
__device__ __nv_bfloat16 g_Xt_hi[DIM_D * DIM_N];    // X^T  [512, 4096]
__device__ __nv_bfloat16 g_Xt_lo[DIM_D * DIM_N];
__device__ __nv_bfloat16 g_CM_hi[DIM_CM * DIM_D];   // [C; M^T]  [6144, 512]
__device__ __nv_bfloat16 g_CM_lo[DIM_CM * DIM_D];
__device__ __nv_bfloat16 g_S_hi[DIM_D * DIM_D];     // S    [512, 512]
__device__ __nv_bfloat16 g_S_lo[DIM_D * DIM_D];
__device__ __nv_bfloat16 g_U_hi[DIM_K * DIM_D];     // U = C@S  [2048, 512]
__device__ __nv_bfloat16 g_U_lo[DIM_K * DIM_D];
__device__ float g_Spart[ZSPLIT * DIM_D * DIM_D];   // split-K partials
__device__ float g_S [DIM_D * DIM_D];
__device__ float g_UT[DIM_CM * DIM_D];              // [U; Tt] = [C;Mt] @ S
__device__ float g_xm2[DIM_M];
__device__ float g_xc2[DIM_K];

// ---------------------------- warp-MMA helpers ------------------------------
__device__ __forceinline__ uint32_t smem_u32(const void* p) {
    uint32_t a;
    asm("{ .reg .u64 t; cvta.to.shared.u64 t, %1; cvt.u32.u64 %0, t; }" : "=r"(a) : "l"(p));
    return a;
}
__device__ __forceinline__ void ldm_x4(uint32_t* r, uint32_t addr) {
    asm volatile("ldmatrix.sync.aligned.m8n8.x4.shared.b16 {%0,%1,%2,%3}, [%4];"
                 : "=r"(r[0]), "=r"(r[1]), "=r"(r[2]), "=r"(r[3]) : "r"(addr));
}
__device__ __forceinline__ void mma_bf16(float* c, const uint32_t* a, const uint32_t* b) {
    asm volatile("mma.sync.aligned.m16n8k16.row.col.f32.bf16.bf16.f32 "
                 "{%0,%1,%2,%3}, {%4,%5,%6,%7}, {%8,%9}, {%0,%1,%2,%3};"
                 : "+f"(c[0]), "+f"(c[1]), "+f"(c[2]), "+f"(c[3])
                 : "r"(a[0]), "r"(a[1]), "r"(a[2]), "r"(a[3]), "r"(b[0]), "r"(b[1]));
}
#define CP_ASYNC16(dst, src) \
    asm volatile("cp.async.cg.shared.global [%0], [%1], 16;" :: "r"(dst), "l"(src))
#define CP_COMMIT() asm volatile("cp.async.commit_group;" ::: "memory")
#define CP_WAIT1()  asm volatile("cp.async.wait_group 1;" ::: "memory")
#define CP_WAIT0()  asm volatile("cp.async.wait_group 0;" ::: "memory")

// ---------------------------------------------------------------------------
// Split-bf16 GEMM via mma.sync:  C[i,j] = sum_k (Ahi+Alo)[i,k] * (Bhi+Blo)[j,k]
// (drops lo*lo; rel err ~2^-18). A [Mo,Ktot] K-major, B [No,Ktot] K-major.
// CTA tile 128x128, K-slab 32, 256 threads = 8 warps (2x4), warp tile 64x32.
// cp.async double-buffered (2 stages x 40KB dynamic smem).
// MMA issue order: product-type outermost -> 16 independent accumulators
// between same-acc reuses (breaks HMMA RAW chains).
// grid = (No/128, Mo/128, zsplits); z slice: kbase = z*kspan, out += z*zstride.
// FUSED: out = sqrt(max(colAdd[col] - 2*acc + rowAdd[row], 0)).
// ---------------------------------------------------------------------------
static constexpr int RSTRIDE = 80;                    // padded smem row stride (bytes)
static constexpr int TILE_BYTES_PAD = 128 * RSTRIDE;  // 10240
static constexpr int STAGE_BYTES = 4 * TILE_BYTES_PAD;// 40960
static constexpr int GEMM_SMEM = 2 * STAGE_BYTES;     // 81920

template <bool FUSED>
__global__ __launch_bounds__(256, 2)
void bf16s_gemm(const __nv_bfloat16* __restrict__ Ahi, const __nv_bfloat16* __restrict__ Alo,
                const __nv_bfloat16* __restrict__ Bhi, const __nv_bfloat16* __restrict__ Blo,
                float* __restrict__ Cout,
                int No, int Ktot, int kspan, size_t zstride,
                const float* __restrict__ rowAdd, const float* __restrict__ colAdd)
{
    extern __shared__ __align__(128) unsigned char smem[];
    const uint32_t sbase = smem_u32(smem);
    const uint32_t OFF_AHI = 0, OFF_ALO = TILE_BYTES_PAD,
                   OFF_BHI = 2 * TILE_BYTES_PAD, OFF_BLO = 3 * TILE_BYTES_PAD;

    const int tid = threadIdx.x;
    const int wid = tid >> 5;
    const int lane = tid & 31;
    const int warp_m = wid >> 2;     // 0..1 -> 64 rows each
    const int warp_n = wid & 3;      // 0..3 -> 32 cols each
    const int rowA0 = blockIdx.y * 128;
    const int rowB0 = blockIdx.x * 128;
    const int kz = blockIdx.z * kspan;
    const int nslabs = kspan / 32;
    Cout += (size_t)blockIdx.z * zstride;

    float acc[4][4][4];
#pragma unroll
    for (int i = 0; i < 4; i++)
#pragma unroll
        for (int j = 0; j < 4; j++)
#pragma unroll
            for (int v = 0; v < 4; v++) acc[i][j][v] = 0.0f;

    // ldmatrix lane addressing (k-invariant parts)
    const int a_row = warp_m * 64 + (lane & 15);
    const uint32_t a_coff = (uint32_t)((lane >> 4) << 4);
    // B x4 pair: pair p covers nj=2p,2p+1
    const int b_row = warp_n * 32 + ((lane >> 4) << 3) + (lane & 7);
    const uint32_t b_coff = (uint32_t)(((lane >> 3) & 1) << 4);

    auto load_slab = [&](int slab, int stage) {
        const int kbase = kz + slab * 32;
        const uint32_t st = (uint32_t)stage * STAGE_BYTES;
#pragma unroll
        for (int i = 0; i < 2; i++) {
            const int idx = tid + i * 256;       // 0..511
            const int r = idx >> 2;
            const int c = idx & 3;
            const size_t aoff = (size_t)(rowA0 + r) * Ktot + kbase + c * 8;
            const size_t boff = (size_t)(rowB0 + r) * Ktot + kbase + c * 8;
            const uint32_t so = st + (uint32_t)(r * RSTRIDE + c * 16);
            CP_ASYNC16(sbase + OFF_AHI + so, Ahi + aoff);
            CP_ASYNC16(sbase + OFF_ALO + so, Alo + aoff);
            CP_ASYNC16(sbase + OFF_BHI + so, Bhi + boff);
            CP_ASYNC16(sbase + OFF_BLO + so, Blo + boff);
        }
    };

    load_slab(0, 0);
    CP_COMMIT();

    for (int slab = 0; slab < nslabs; slab++) {
        const int cur = slab & 1;
        if (slab + 1 < nslabs) {
            load_slab(slab + 1, cur ^ 1);
            CP_COMMIT();
            CP_WAIT1();
        } else {
            CP_WAIT0();
        }
        __syncthreads();          // slab data visible to all warps

        const uint32_t st = (uint32_t)cur * STAGE_BYTES;
#pragma unroll
        for (int kk = 0; kk < 2; kk++) {         // two k16 steps per slab
            const uint32_t kcol = kk * 32;
            uint32_t a_hi[4][4], a_lo[4][4], b_hi[2][4], b_lo[2][4];
#pragma unroll
            for (int mi = 0; mi < 4; mi++) {
                const uint32_t ar = st + (uint32_t)((a_row + mi * 16) * RSTRIDE) + kcol + a_coff;
                ldm_x4(a_hi[mi], sbase + OFF_AHI + ar);
                ldm_x4(a_lo[mi], sbase + OFF_ALO + ar);
            }
#pragma unroll
            for (int p = 0; p < 2; p++) {        // nj pairs {0,1}, {2,3}
                const uint32_t br = st + (uint32_t)((b_row + p * 16) * RSTRIDE) + kcol + b_coff;
                ldm_x4(b_hi[p], sbase + OFF_BHI + br);
                ldm_x4(b_lo[p], sbase + OFF_BLO + br);
            }
            // Product-type outermost: 16 independent accs between same-acc MMAs.
#pragma unroll
            for (int prod = 0; prod < 3; prod++) {
#pragma unroll
                for (int mi = 0; mi < 4; mi++)
#pragma unroll
                    for (int nj = 0; nj < 4; nj++) {
                        const uint32_t* av = (prod == 2) ? a_lo[mi] : a_hi[mi];
                        const uint32_t* bv = (prod == 1) ? &b_lo[nj >> 1][(nj & 1) * 2]
                                                         : &b_hi[nj >> 1][(nj & 1) * 2];
                        mma_bf16(acc[mi][nj], av, bv);
                    }
            }
        }
        __syncthreads();          // compute done before stage is overwritten
    }

    // Epilogue. c-frag layout: c0,c1 -> row lane/4,   cols (lane%4)*2 + {0,1}
    //                          c2,c3 -> row lane/4+8, same cols
    const int er0 = rowA0 + warp_m * 64 + (lane >> 2);
    const int ec0 = rowB0 + warp_n * 32 + (lane & 3) * 2;
#pragma unroll
    for (int mi = 0; mi < 4; mi++) {
#pragma unroll
        for (int half = 0; half < 2; half++) {
            const int row = er0 + mi * 16 + half * 8;
            float radd = 0.0f;
            if (FUSED) radd = rowAdd[row];
#pragma unroll
            for (int nj = 0; nj < 4; nj++) {
                const int col = ec0 + nj * 8;
                float2 v;
                v.x = acc[mi][nj][half * 2 + 0];
                v.y = acc[mi][nj][half * 2 + 1];
                if (FUSED) {
                    const float2 ca = *(const float2*)(colAdd + col);
                    v.x = sqrtf(fmaxf(ca.x - 2.0f * v.x + radd, 0.0f));
                    v.y = sqrtf(fmaxf(ca.y - 2.0f * v.y + radd, 0.0f));
                }
                *(float2*)(Cout + (size_t)row * No + col) = v;
            }
        }
    }
}

// ------------------------- conversion / small kernels -----------------------
__global__ void split_kernel(const float* __restrict__ in,
                             __nv_bfloat16* __restrict__ hi,
                             __nv_bfloat16* __restrict__ lo, int n)
{
    const int i = blockIdx.x * blockDim.x + threadIdx.x;
    if (i >= n) return;
    const float x = in[i];
    const __nv_bfloat16 h = __float2bfloat16_rn(x);
    hi[i] = h;
    lo[i] = __float2bfloat16_rn(x - __bfloat162float(h));
}

// in [R,C] fp32 -> hi/lo [C,R] bf16 (transpose)
__global__ void split_transpose_kernel(const float* __restrict__ in,
                                       __nv_bfloat16* __restrict__ hi,
                                       __nv_bfloat16* __restrict__ lo, int R, int C)
{
    __shared__ float t[32][33];
    const int x = blockIdx.x * 32 + threadIdx.x;  // col in input
    const int y0 = blockIdx.y * 32;
#pragma unroll
    for (int j = 0; j < 32; j += 8)
        t[threadIdx.y + j][threadIdx.x] = in[(size_t)(y0 + threadIdx.y + j) * C + x];
    __syncthreads();
#pragma unroll
    for (int j = 0; j < 32; j += 8) {
        const int c = blockIdx.x * 32 + threadIdx.y + j;  // out row (= input col)
        const int r = y0 + threadIdx.x;                   // out col (= input row)
        const float v = t[threadIdx.x][threadIdx.y + j];
        const __nv_bfloat16 h = __float2bfloat16_rn(v);
        hi[(size_t)c * R + r] = h;
        lo[(size_t)c * R + r] = __float2bfloat16_rn(v - __bfloat162float(h));
    }
}

__global__ void reduce_z_kernel(const float* __restrict__ part, float* __restrict__ out, int n)
{
    const int i = blockIdx.x * blockDim.x + threadIdx.x;
    if (i >= n) return;
    float acc = 0.0f;
#pragma unroll
    for (int z = 0; z < ZSPLIT; z++) acc += part[i + (size_t)z * n];
    out[i] = acc;
}

// xc2[k] = sum_d A[k,d]*B[k,d]  (fp32 x fp32, one warp per row)
__global__ void row_dot_kernel(const float* __restrict__ A, const float* __restrict__ B,
                               float* __restrict__ out, int rows, int cols)
{
    const int row = blockIdx.x * (blockDim.x >> 5) + (threadIdx.x >> 5);
    const int lane = threadIdx.x & 31;
    if (row >= rows) return;
    float acc = 0.0f;
    for (int c = lane; c < cols; c += 32)
        acc = fmaf(A[(size_t)row * cols + c], B[(size_t)row * cols + c], acc);
#pragma unroll
    for (int o = 16; o > 0; o >>= 1) acc += __shfl_xor_sync(0xFFFFFFFFu, acc, o);
    if (lane == 0) out[row] = acc;
}

// xm2[m] = sum_d (hi+lo)[m,d] * B[m,d]
__global__ void row_dot_split_kernel(const __nv_bfloat16* __restrict__ Ahi,
                                     const __nv_bfloat16* __restrict__ Alo,
                                     const float* __restrict__ B,
                                     float* __restrict__ out, int rows, int cols)
{
    const int row = blockIdx.x * (blockDim.x >> 5) + (threadIdx.x >> 5);
    const int lane = threadIdx.x & 31;
    if (row >= rows) return;
    float acc = 0.0f;
    for (int c = lane; c < cols; c += 32) {
        const size_t o = (size_t)row * cols + c;
        const float a = __bfloat162float(Ahi[o]) + __bfloat162float(Alo[o]);
        acc = fmaf(a, B[o], acc);
    }
#pragma unroll
    for (int o = 16; o > 0; o >>= 1) acc += __shfl_xor_sync(0xFFFFFFFFu, acc, o);
    if (lane == 0) out[row] = acc;
}

// --------------------------------- launch ----------------------------------
extern "C" void kernel_launch(void* const* d_in, const int* in_sizes, int n_in,
                              void* d_out, int out_size)
{
    const float* X = (const float*)d_in[0];  // [4096, 512]
    const float* M = (const float*)d_in[1];  // [512, 4096]
    const float* C = (const float*)d_in[2];  // [2048, 512]
    float* out = (float*)d_out;              // [2048, 4096]

    static bool attr_done = false;
    if (!attr_done) {
        cudaFuncSetAttribute(bf16s_gemm<false>, cudaFuncAttributeMaxDynamicSharedMemorySize, GEMM_SMEM);
        cudaFuncSetAttribute(bf16s_gemm<true>,  cudaFuncAttributeMaxDynamicSharedMemorySize, GEMM_SMEM);
        attr_done = true;
    }

    __nv_bfloat16 *Xt_hi, *Xt_lo, *CM_hi, *CM_lo, *S_hi, *S_lo, *U_hi, *U_lo;
    float *Spart, *S, *UT, *xm2, *xc2;
    cudaGetSymbolAddress((void**)&Xt_hi, g_Xt_hi);
    cudaGetSymbolAddress((void**)&Xt_lo, g_Xt_lo);
    cudaGetSymbolAddress((void**)&CM_hi, g_CM_hi);
    cudaGetSymbolAddress((void**)&CM_lo, g_CM_lo);
    cudaGetSymbolAddress((void**)&S_hi,  g_S_hi);
    cudaGetSymbolAddress((void**)&S_lo,  g_S_lo);
    cudaGetSymbolAddress((void**)&U_hi,  g_U_hi);
    cudaGetSymbolAddress((void**)&U_lo,  g_U_lo);
    cudaGetSymbolAddress((void**)&Spart, g_Spart);
    cudaGetSymbolAddress((void**)&S,     g_S);
    cudaGetSymbolAddress((void**)&UT,    g_UT);
    cudaGetSymbolAddress((void**)&xm2,   g_xm2);
    cudaGetSymbolAddress((void**)&xc2,   g_xc2);

    __nv_bfloat16* Mt_hi = CM_hi + (size_t)DIM_K * DIM_D;  // rows 2048..6143
    __nv_bfloat16* Mt_lo = CM_lo + (size_t)DIM_K * DIM_D;
    float* Tt = UT + (size_t)DIM_K * DIM_D;

    // 1) transposed splits: Xt [512,4096]; stacked CM = [C; M^T] [6144,512]
    split_transpose_kernel<<<dim3(DIM_D / 32, DIM_N / 32), dim3(32, 8)>>>(X, Xt_hi, Xt_lo, DIM_N, DIM_D);
    split_kernel<<<(DIM_K * DIM_D) / 256, 256>>>(C, CM_hi, CM_lo, DIM_K * DIM_D);
    split_transpose_kernel<<<dim3(DIM_M / 32, DIM_D / 32), dim3(32, 8)>>>(M, Mt_hi, Mt_lo, DIM_D, DIM_M);

    // 2) S = Xt @ Xt^T  [512,512], K=4096, split-K=16
    bf16s_gemm<false><<<dim3(DIM_D / 128, DIM_D / 128, ZSPLIT), 256, GEMM_SMEM>>>(
        Xt_hi, Xt_lo, Xt_hi, Xt_lo, Spart,
        DIM_D, DIM_N, DIM_N / ZSPLIT, (size_t)DIM_D * DIM_D, nullptr, nullptr);
    reduce_z_kernel<<<(DIM_D * DIM_D) / 256, 256>>>(Spart, S, DIM_D * DIM_D);
    split_kernel<<<(DIM_D * DIM_D) / 256, 256>>>(S, S_hi, S_lo, DIM_D * DIM_D);

    // 3) UT = [C; Mt] @ S  [6144,512]  (S symmetric -> S rows valid K-major B)
    bf16s_gemm<false><<<dim3(DIM_D / 128, DIM_CM / 128, 1), 256, GEMM_SMEM>>>(
        CM_hi, CM_lo, S_hi, S_lo, UT, DIM_D, DIM_D, DIM_D, 0, nullptr, nullptr);
    split_kernel<<<(DIM_K * DIM_D) / 256, 256>>>(UT, U_hi, U_lo, DIM_K * DIM_D);

    // 4) xm2[m] = m^T S m ; xc2[k] = c_k^T S c_k
    row_dot_split_kernel<<<DIM_M / 8, 256>>>(Mt_hi, Mt_lo, Tt, xm2, DIM_M, DIM_D);
    row_dot_kernel<<<DIM_K / 8, 256>>>(C, UT, xc2, DIM_K, DIM_D);

    // 5) out[k,m] = sqrt(max(xm2[m] - 2*(U @ Mt^T)[k,m] + xc2[k], 0))
    bf16s_gemm<true><<<dim3(DIM_M / 128, DIM_K / 128, 1), 256, GEMM_SMEM>>>(
        U_hi, U_lo, Mt_hi, Mt_lo, out, DIM_M, DIM_D, DIM_D, 0, xc2, xm2);
}

// round 7
// speedup vs baseline: 5.4350x; 1.1562x over previous
#include <cuda_runtime.h>
#include <cuda_bf16.h>
#include <cstdint>
#include <math.h>

// Problem dims (fixed)
static constexpr int DIM_N = 4096;  // samples
static constexpr int DIM_D = 512;   // feature dim
static constexpr int DIM_M = 4096;  // M columns
static constexpr int DIM_K = 2048;  // centroids
static constexpr int ZSPLIT = 16;   // split-K factor for S = X^T X
static constexpr int DIM_CM = DIM_K + DIM_M;  // stacked [C; Mt] rows = 6144

// ---------------- scratch (device globals; allocation-free) ----------------
__device__ __nv_bfloat16 g_Xt_hi[DIM_D * DIM_N];    // X^T  [512, 4096]
__device__ __nv_bfloat16 g_Xt_lo[DIM_D * DIM_N];
__device__ __nv_bfloat16 g_CM_hi[DIM_CM * DIM_D];   // [C; M^T]  [6144, 512]
__device__ __nv_bfloat16 g_CM_lo[DIM_CM * DIM_D];
__device__ __nv_bfloat16 g_S_hi[DIM_D * DIM_D];     // S    [512, 512]
__device__ __nv_bfloat16 g_S_lo[DIM_D * DIM_D];
__device__ __nv_bfloat16 g_U_hi[DIM_K * DIM_D];     // U = C@S  [2048, 512]
__device__ __nv_bfloat16 g_U_lo[DIM_K * DIM_D];
__device__ float g_Spart[ZSPLIT * DIM_D * DIM_D];   // split-K partials
__device__ float g_dotp[4 * DIM_CM];                // per-col-band dot partials
__device__ float g_xm2[DIM_M];
__device__ float g_xc2[DIM_K];

// ---------------------------- warp-MMA helpers ------------------------------
__device__ __forceinline__ uint32_t smem_u32(const void* p) {
    uint32_t a;
    asm("{ .reg .u64 t; cvta.to.shared.u64 t, %1; cvt.u32.u64 %0, t; }" : "=r"(a) : "l"(p));
    return a;
}
__device__ __forceinline__ void ldm_x4(uint32_t* r, uint32_t addr) {
    asm volatile("ldmatrix.sync.aligned.m8n8.x4.shared.b16 {%0,%1,%2,%3}, [%4];"
                 : "=r"(r[0]), "=r"(r[1]), "=r"(r[2]), "=r"(r[3]) : "r"(addr));
}
__device__ __forceinline__ void mma_bf16(float* c, const uint32_t* a, const uint32_t* b) {
    asm volatile("mma.sync.aligned.m16n8k16.row.col.f32.bf16.bf16.f32 "
                 "{%0,%1,%2,%3}, {%4,%5,%6,%7}, {%8,%9}, {%0,%1,%2,%3};"
                 : "+f"(c[0]), "+f"(c[1]), "+f"(c[2]), "+f"(c[3])
                 : "r"(a[0]), "r"(a[1]), "r"(a[2]), "r"(a[3]), "r"(b[0]), "r"(b[1]));
}
#define CP_ASYNC16(dst, src) \
    asm volatile("cp.async.cg.shared.global [%0], [%1], 16;" :: "r"(dst), "l"(src))
#define CP_COMMIT() asm volatile("cp.async.commit_group;" ::: "memory")
#define CP_WAIT1()  asm volatile("cp.async.wait_group 1;" ::: "memory")
#define CP_WAIT0()  asm volatile("cp.async.wait_group 0;" ::: "memory")

// 64B-row smem layout with XOR swizzle (ldmatrix conflict-free, no padding).
__device__ __forceinline__ uint32_t swz(uint32_t row, uint32_t col) {
    return row * 64 + (col ^ ((row & 6) << 3));
}

// ---------------------------------------------------------------------------
// Split-bf16 GEMM via mma.sync:  G[i,j] = sum_k (Ahi+Alo)[i,k] * (Bhi+Blo)[j,k]
// (drops lo*lo; rel err ~2^-18). A [Mo,Ktot] K-major, B [No,Ktot] K-major.
// CTA tile 128x128, K-slab 32, 256 threads = 8 warps (2x4), warp tile 64x32.
// 3-stage cp.async pipeline, swizzled 32KB stages (96KB smem, 2 CTA/SM).
// MODE 0: write fp32 Cout (with z-split offsets).
// MODE 1: fused distance epilogue: out = sqrt(max(colAdd[c] - 2g + rowAdd[r],0)).
// MODE 2: UT mode (Ktot==No==512): write bf16 split of G to Uhi/Ulo for rows
//         < DIM_K, and emit per-CTA-band dot partials
//         dotp[bx*DIM_CM + row] = sum_{c in band} Afp32[row,c] * G[row,c].
// ---------------------------------------------------------------------------
static constexpr int TILE_BYTES = 128 * 64;            // 8192
static constexpr int STAGE_BYTES = 4 * TILE_BYTES;     // 32768
static constexpr int GEMM_SMEM = 3 * STAGE_BYTES;      // 98304

template <int MODE>
__global__ __launch_bounds__(256, 2)
void bf16s_gemm(const __nv_bfloat16* __restrict__ Ahi, const __nv_bfloat16* __restrict__ Alo,
                const __nv_bfloat16* __restrict__ Bhi, const __nv_bfloat16* __restrict__ Blo,
                float* __restrict__ Cout,
                int No, int Ktot, int kspan, size_t zstride,
                const float* __restrict__ rowAdd, const float* __restrict__ colAdd,
                __nv_bfloat16* __restrict__ Uhi, __nv_bfloat16* __restrict__ Ulo,
                float* __restrict__ dotp)
{
    extern __shared__ __align__(128) unsigned char smem[];
    const uint32_t sbase = smem_u32(smem);
    const uint32_t OFF_AHI = 0, OFF_ALO = TILE_BYTES,
                   OFF_BHI = 2 * TILE_BYTES, OFF_BLO = 3 * TILE_BYTES;

    const int tid = threadIdx.x;
    const int wid = tid >> 5;
    const int lane = tid & 31;
    const int warp_m = wid >> 2;     // 0..1 -> 64 rows each
    const int warp_n = wid & 3;      // 0..3 -> 32 cols each
    const int rowA0 = blockIdx.y * 128;
    const int rowB0 = blockIdx.x * 128;
    const int kz = blockIdx.z * kspan;
    const int nslabs = kspan / 32;
    if (MODE == 0) Cout += (size_t)blockIdx.z * zstride;

    float acc[4][4][4];
#pragma unroll
    for (int i = 0; i < 4; i++)
#pragma unroll
        for (int j = 0; j < 4; j++)
#pragma unroll
            for (int v = 0; v < 4; v++) acc[i][j][v] = 0.0f;

    // ldmatrix lane addressing (k-invariant parts)
    const int a_row = warp_m * 64 + (lane & 15);
    const uint32_t a_coff = (uint32_t)((lane >> 4) << 4);
    const int b_row = warp_n * 32 + ((lane >> 4) << 3) + (lane & 7);
    const uint32_t b_coff = (uint32_t)(((lane >> 3) & 1) << 4);

    auto load_slab = [&](int slab, int stage) {
        const int kbase = kz + slab * 32;
        const uint32_t st = (uint32_t)stage * STAGE_BYTES;
#pragma unroll
        for (int i = 0; i < 2; i++) {
            const int idx = tid + i * 256;       // 0..511
            const int r = idx >> 2;
            const int c = idx & 3;
            const size_t aoff = (size_t)(rowA0 + r) * Ktot + kbase + c * 8;
            const size_t boff = (size_t)(rowB0 + r) * Ktot + kbase + c * 8;
            const uint32_t so = st + swz((uint32_t)r, (uint32_t)(c * 16));
            CP_ASYNC16(sbase + OFF_AHI + so, Ahi + aoff);
            CP_ASYNC16(sbase + OFF_ALO + so, Alo + aoff);
            CP_ASYNC16(sbase + OFF_BHI + so, Bhi + boff);
            CP_ASYNC16(sbase + OFF_BLO + so, Blo + boff);
        }
    };

    // 3-stage pipeline: prefetch distance 2.
    load_slab(0, 0); CP_COMMIT();
    if (nslabs > 1) { load_slab(1, 1); CP_COMMIT(); }

    for (int slab = 0; slab < nslabs; slab++) {
        if (slab + 2 < nslabs) { CP_WAIT1(); } else { CP_WAIT0(); }
        __syncthreads();          // slab data visible; stage (slab+2)%3 free
        if (slab + 2 < nslabs) {
            load_slab(slab + 2, (slab + 2) % 3);
            CP_COMMIT();
        }

        const uint32_t st = (uint32_t)(slab % 3) * STAGE_BYTES;
#pragma unroll
        for (int kk = 0; kk < 2; kk++) {         // two k16 steps per slab
            const uint32_t kcol = kk * 32;
            uint32_t a_hi[4][4], a_lo[4][4], b_hi[2][4], b_lo[2][4];
#pragma unroll
            for (int mi = 0; mi < 4; mi++) {
                const uint32_t row = (uint32_t)(a_row + mi * 16);
                const uint32_t ar = st + swz(row, kcol + a_coff);
                ldm_x4(a_hi[mi], sbase + OFF_AHI + ar);
                ldm_x4(a_lo[mi], sbase + OFF_ALO + ar);
            }
#pragma unroll
            for (int p = 0; p < 2; p++) {        // nj pairs {0,1}, {2,3}
                const uint32_t row = (uint32_t)(b_row + p * 16);
                const uint32_t br = st + swz(row, kcol + b_coff);
                ldm_x4(b_hi[p], sbase + OFF_BHI + br);
                ldm_x4(b_lo[p], sbase + OFF_BLO + br);
            }
#pragma unroll
            for (int prod = 0; prod < 3; prod++) {
#pragma unroll
                for (int mi = 0; mi < 4; mi++)
#pragma unroll
                    for (int nj = 0; nj < 4; nj++) {
                        const uint32_t* av = (prod == 2) ? a_lo[mi] : a_hi[mi];
                        const uint32_t* bv = (prod == 1) ? &b_lo[nj >> 1][(nj & 1) * 2]
                                                         : &b_hi[nj >> 1][(nj & 1) * 2];
                        mma_bf16(acc[mi][nj], av, bv);
                    }
            }
        }
    }

    // ---------------- epilogue ----------------
    // c-frag layout: c0,c1 -> row lane/4, cols (lane%4)*2+{0,1}; c2,c3 -> row+8
    const int er0 = rowA0 + warp_m * 64 + (lane >> 2);
    const int ec0 = rowB0 + warp_n * 32 + (lane & 3) * 2;

    if (MODE == 2) {
        __syncthreads();                          // mainloop smem reuse
        float* sm_dot = (float*)smem;             // [128 rows][4 warp_n]
#pragma unroll
        for (int mi = 0; mi < 4; mi++) {
#pragma unroll
            for (int half = 0; half < 2; half++) {
                const int row = er0 + mi * 16 + half * 8;
                float rs = 0.0f;
#pragma unroll
                for (int nj = 0; nj < 4; nj++) {
                    const int col = ec0 + nj * 8;
                    float2 v;
                    v.x = acc[mi][nj][half * 2 + 0];
                    v.y = acc[mi][nj][half * 2 + 1];
                    // A value at (row, col) in fp32 (hi+lo)
                    const size_t o = (size_t)row * Ktot + col;
                    const float ax = __bfloat162float(Ahi[o])     + __bfloat162float(Alo[o]);
                    const float ay = __bfloat162float(Ahi[o + 1]) + __bfloat162float(Alo[o + 1]);
                    rs = fmaf(ax, v.x, rs);
                    rs = fmaf(ay, v.y, rs);
                    if (row < DIM_K) {            // write split U
                        const __nv_bfloat16 hx = __float2bfloat16_rn(v.x);
                        const __nv_bfloat16 hy = __float2bfloat16_rn(v.y);
                        __nv_bfloat162 h2; h2.x = hx; h2.y = hy;
                        __nv_bfloat162 l2;
                        l2.x = __float2bfloat16_rn(v.x - __bfloat162float(hx));
                        l2.y = __float2bfloat16_rn(v.y - __bfloat162float(hy));
                        const size_t uo = (size_t)row * DIM_D + col;
                        *(__nv_bfloat162*)(Uhi + uo) = h2;
                        *(__nv_bfloat162*)(Ulo + uo) = l2;
                    }
                }
                rs += __shfl_xor_sync(0xFFFFFFFFu, rs, 1);
                rs += __shfl_xor_sync(0xFFFFFFFFu, rs, 2);
                if ((lane & 3) == 0) {
                    const int lr = warp_m * 64 + mi * 16 + half * 8 + (lane >> 2);
                    sm_dot[lr * 4 + warp_n] = rs;
                }
            }
        }
        __syncthreads();
        if (tid < 128) {
            const float s = sm_dot[tid * 4] + sm_dot[tid * 4 + 1]
                          + sm_dot[tid * 4 + 2] + sm_dot[tid * 4 + 3];
            dotp[(size_t)blockIdx.x * DIM_CM + rowA0 + tid] = s;
        }
        return;
    }

#pragma unroll
    for (int mi = 0; mi < 4; mi++) {
#pragma unroll
        for (int half = 0; half < 2; half++) {
            const int row = er0 + mi * 16 + half * 8;
            float radd = 0.0f;
            if (MODE == 1) radd = rowAdd[row];
#pragma unroll
            for (int nj = 0; nj < 4; nj++) {
                const int col = ec0 + nj * 8;
                float2 v;
                v.x = acc[mi][nj][half * 2 + 0];
                v.y = acc[mi][nj][half * 2 + 1];
                if (MODE == 1) {
                    const float2 ca = *(const float2*)(colAdd + col);
                    v.x = sqrtf(fmaxf(ca.x - 2.0f * v.x + radd, 0.0f));
                    v.y = sqrtf(fmaxf(ca.y - 2.0f * v.y + radd, 0.0f));
                }
                *(float2*)(Cout + (size_t)row * No + col) = v;
            }
        }
    }
}

// ------------------------- conversion / small kernels -----------------------
__global__ void split_kernel(const float* __restrict__ in,
                             __nv_bfloat16* __restrict__ hi,
                             __nv_bfloat16* __restrict__ lo, int n)
{
    const int i = blockIdx.x * blockDim.x + threadIdx.x;
    if (i >= n) return;
    const float x = in[i];
    const __nv_bfloat16 h = __float2bfloat16_rn(x);
    hi[i] = h;
    lo[i] = __float2bfloat16_rn(x - __bfloat162float(h));
}

// in [R,C] fp32 -> hi/lo [C,R] bf16 (transpose)
__global__ void split_transpose_kernel(const float* __restrict__ in,
                                       __nv_bfloat16* __restrict__ hi,
                                       __nv_bfloat16* __restrict__ lo, int R, int C)
{
    __shared__ float t[32][33];
    const int x = blockIdx.x * 32 + threadIdx.x;  // col in input
    const int y0 = blockIdx.y * 32;
#pragma unroll
    for (int j = 0; j < 32; j += 8)
        t[threadIdx.y + j][threadIdx.x] = in[(size_t)(y0 + threadIdx.y + j) * C + x];
    __syncthreads();
#pragma unroll
    for (int j = 0; j < 32; j += 8) {
        const int c = blockIdx.x * 32 + threadIdx.y + j;  // out row (= input col)
        const int r = y0 + threadIdx.x;                   // out col (= input row)
        const float v = t[threadIdx.x][threadIdx.y + j];
        const __nv_bfloat16 h = __float2bfloat16_rn(v);
        hi[(size_t)c * R + r] = h;
        lo[(size_t)c * R + r] = __float2bfloat16_rn(v - __bfloat162float(h));
    }
}

// sum split-K partials of S and split to bf16 hi/lo in one pass
__global__ void reduce_split_kernel(const float* __restrict__ part,
                                    __nv_bfloat16* __restrict__ hi,
                                    __nv_bfloat16* __restrict__ lo, int n)
{
    const int i = blockIdx.x * blockDim.x + threadIdx.x;
    if (i >= n) return;
    float acc = 0.0f;
#pragma unroll
    for (int z = 0; z < ZSPLIT; z++) acc += part[i + (size_t)z * n];
    const __nv_bfloat16 h = __float2bfloat16_rn(acc);
    hi[i] = h;
    lo[i] = __float2bfloat16_rn(acc - __bfloat162float(h));
}

// xc2/xm2 = sum of 4 col-band partials
__global__ void combine_dots_kernel(const float* __restrict__ dotp,
                                    float* __restrict__ xc2, float* __restrict__ xm2)
{
    const int i = blockIdx.x * blockDim.x + threadIdx.x;
    if (i >= DIM_CM) return;
    const float s = dotp[i] + dotp[DIM_CM + i] + dotp[2 * DIM_CM + i] + dotp[3 * DIM_CM + i];
    if (i < DIM_K) xc2[i] = s;
    else           xm2[i - DIM_K] = s;
}

// --------------------------------- launch ----------------------------------
extern "C" void kernel_launch(void* const* d_in, const int* in_sizes, int n_in,
                              void* d_out, int out_size)
{
    const float* X = (const float*)d_in[0];  // [4096, 512]
    const float* M = (const float*)d_in[1];  // [512, 4096]
    const float* C = (const float*)d_in[2];  // [2048, 512]
    float* out = (float*)d_out;              // [2048, 4096]

    static bool attr_done = false;
    if (!attr_done) {
        cudaFuncSetAttribute(bf16s_gemm<0>, cudaFuncAttributeMaxDynamicSharedMemorySize, GEMM_SMEM);
        cudaFuncSetAttribute(bf16s_gemm<1>, cudaFuncAttributeMaxDynamicSharedMemorySize, GEMM_SMEM);
        cudaFuncSetAttribute(bf16s_gemm<2>, cudaFuncAttributeMaxDynamicSharedMemorySize, GEMM_SMEM);
        attr_done = true;
    }

    __nv_bfloat16 *Xt_hi, *Xt_lo, *CM_hi, *CM_lo, *S_hi, *S_lo, *U_hi, *U_lo;
    float *Spart, *dotp, *xm2, *xc2;
    cudaGetSymbolAddress((void**)&Xt_hi, g_Xt_hi);
    cudaGetSymbolAddress((void**)&Xt_lo, g_Xt_lo);
    cudaGetSymbolAddress((void**)&CM_hi, g_CM_hi);
    cudaGetSymbolAddress((void**)&CM_lo, g_CM_lo);
    cudaGetSymbolAddress((void**)&S_hi,  g_S_hi);
    cudaGetSymbolAddress((void**)&S_lo,  g_S_lo);
    cudaGetSymbolAddress((void**)&U_hi,  g_U_hi);
    cudaGetSymbolAddress((void**)&U_lo,  g_U_lo);
    cudaGetSymbolAddress((void**)&Spart, g_Spart);
    cudaGetSymbolAddress((void**)&dotp,  g_dotp);
    cudaGetSymbolAddress((void**)&xm2,   g_xm2);
    cudaGetSymbolAddress((void**)&xc2,   g_xc2);

    __nv_bfloat16* Mt_hi = CM_hi + (size_t)DIM_K * DIM_D;  // rows 2048..6143
    __nv_bfloat16* Mt_lo = CM_lo + (size_t)DIM_K * DIM_D;

    // 1) transposed splits: Xt [512,4096]; stacked CM = [C; M^T] [6144,512]
    split_transpose_kernel<<<dim3(DIM_D / 32, DIM_N / 32), dim3(32, 8)>>>(X, Xt_hi, Xt_lo, DIM_N, DIM_D);
    split_kernel<<<(DIM_K * DIM_D) / 256, 256>>>(C, CM_hi, CM_lo, DIM_K * DIM_D);
    split_transpose_kernel<<<dim3(DIM_M / 32, DIM_D / 32), dim3(32, 8)>>>(M, Mt_hi, Mt_lo, DIM_D, DIM_M);

    // 2) S = Xt @ Xt^T  [512,512], K=4096, split-K=16
    bf16s_gemm<0><<<dim3(DIM_D / 128, DIM_D / 128, ZSPLIT), 256, GEMM_SMEM>>>(
        Xt_hi, Xt_lo, Xt_hi, Xt_lo, Spart,
        DIM_D, DIM_N, DIM_N / ZSPLIT, (size_t)DIM_D * DIM_D,
        nullptr, nullptr, nullptr, nullptr, nullptr);
    reduce_split_kernel<<<(DIM_D * DIM_D) / 256, 256>>>(Spart, S_hi, S_lo, DIM_D * DIM_D);

    // 3) UT = [C; Mt] @ S  (MODE2: writes U_hi/U_lo for C rows + dot partials;
    //    Tt never materialized)
    bf16s_gemm<2><<<dim3(DIM_D / 128, DIM_CM / 128, 1), 256, GEMM_SMEM>>>(
        CM_hi, CM_lo, S_hi, S_lo, nullptr, DIM_D, DIM_D, DIM_D, 0,
        nullptr, nullptr, U_hi, U_lo, dotp);

    // 4) xc2[k] = c_k^T S c_k ; xm2[m] = m^T S m
    combine_dots_kernel<<<(DIM_CM + 255) / 256, 256>>>(dotp, xc2, xm2);

    // 5) out[k,m] = sqrt(max(xm2[m] - 2*(U @ Mt^T)[k,m] + xc2[k], 0))
    bf16s_gemm<1><<<dim3(DIM_M / 128, DIM_K / 128, 1), 256, GEMM_SMEM>>>(
        U_hi, U_lo, Mt_hi, Mt_lo, out, DIM_M, DIM_D, DIM_D, 0,
        xc2, xm2, nullptr, nullptr, nullptr);
}

// round 8
// speedup vs baseline: 7.0145x; 1.2906x over previous
#include <cuda_runtime.h>
#include <cuda_fp16.h>
#include <cstdint>
#include <math.h>

// Problem dims (fixed)
static constexpr int DIM_N = 4096;  // samples
static constexpr int DIM_D = 512;   // feature dim
static constexpr int DIM_M = 4096;  // M columns
static constexpr int DIM_K = 2048;  // centroids
static constexpr int ZSPLIT = 16;   // split-K factor for S = X^T X
static constexpr int DIM_CM = DIM_K + DIM_M;  // stacked [C; Mt] rows = 6144

// ---------------- scratch (device globals; allocation-free) ----------------
__device__ __half g_Xt_hi[DIM_D * DIM_N];    // X^T  [512, 4096]
__device__ __half g_Xt_lo[DIM_D * DIM_N];
__device__ __half g_CM_hi[DIM_CM * DIM_D];   // [C; M^T]  [6144, 512]
__device__ __half g_CM_lo[DIM_CM * DIM_D];
__device__ __half g_S_hi[DIM_D * DIM_D];     // S    [512, 512]
__device__ __half g_S_lo[DIM_D * DIM_D];
__device__ __half g_U_hi[DIM_K * DIM_D];     // U = C@S  [2048, 512]
__device__ float g_Spart[ZSPLIT * DIM_D * DIM_D];   // split-K partials
__device__ float g_dotp[4 * DIM_CM];                // per-col-band dot partials
__device__ float g_xm2[DIM_M];
__device__ float g_xc2[DIM_K];

// ---------------------------- warp-MMA helpers ------------------------------
__device__ __forceinline__ uint32_t smem_u32(const void* p) {
    uint32_t a;
    asm("{ .reg .u64 t; cvta.to.shared.u64 t, %1; cvt.u32.u64 %0, t; }" : "=r"(a) : "l"(p));
    return a;
}
__device__ __forceinline__ void ldm_x4(uint32_t* r, uint32_t addr) {
    asm volatile("ldmatrix.sync.aligned.m8n8.x4.shared.b16 {%0,%1,%2,%3}, [%4];"
                 : "=r"(r[0]), "=r"(r[1]), "=r"(r[2]), "=r"(r[3]) : "r"(addr));
}
__device__ __forceinline__ void mma_f16(float* c, const uint32_t* a, const uint32_t* b) {
    asm volatile("mma.sync.aligned.m16n8k16.row.col.f32.f16.f16.f32 "
                 "{%0,%1,%2,%3}, {%4,%5,%6,%7}, {%8,%9}, {%0,%1,%2,%3};"
                 : "+f"(c[0]), "+f"(c[1]), "+f"(c[2]), "+f"(c[3])
                 : "r"(a[0]), "r"(a[1]), "r"(a[2]), "r"(a[3]), "r"(b[0]), "r"(b[1]));
}
#define CP_ASYNC16(dst, src) \
    asm volatile("cp.async.cg.shared.global [%0], [%1], 16;" :: "r"(dst), "l"(src))
#define CP_COMMIT() asm volatile("cp.async.commit_group;" ::: "memory")
#define CP_WAIT2()  asm volatile("cp.async.wait_group 2;" ::: "memory")
#define CP_WAIT1()  asm volatile("cp.async.wait_group 1;" ::: "memory")
#define CP_WAIT0()  asm volatile("cp.async.wait_group 0;" ::: "memory")

// 64B-row smem layout with XOR swizzle (ldmatrix conflict-free, no padding).
__device__ __forceinline__ uint32_t swz(uint32_t row, uint32_t col) {
    return row * 64 + (col ^ ((row & 6) << 3));
}

// ---------------------------------------------------------------------------
// fp16 2-product GEMM via mma.sync:
//   G[i,j] = sum_k Ahi[i,k] * (Bhi+Blo)[j,k]      (error ~2^-12 relative)
// A [Mo,Ktot] K-major fp16 (hi plane only), B [No,Ktot] K-major fp16 hi+lo.
// CTA tile 128x128, K-slab 32, 256 threads = 8 warps (2x4), warp tile 64x32.
// 4-stage cp.async pipeline, swizzled 24KB stages (96KB smem, 2 CTA/SM).
// MODE 0: write fp32 Cout (with z-split offsets).
// MODE 1: fused distance epilogue: out = sqrt(max(colAdd[c] - 2g + rowAdd[r],0)).
// MODE 2: UT mode (Ktot==No==512): write fp16 G to Uhi for rows < DIM_K, and
//         emit per-CTA-band dot partials
//         dotp[bx*DIM_CM + row] = sum_{c in band} Afp32[row,c] * G[row,c],
//         where Afp32 is reconstructed from Ahi+Alo.
// ---------------------------------------------------------------------------
static constexpr int TILE_BYTES = 128 * 64;            // 8192
static constexpr int STAGE_BYTES = 3 * TILE_BYTES;     // 24576
static constexpr int GEMM_SMEM = 4 * STAGE_BYTES;      // 98304

template <int MODE>
__global__ __launch_bounds__(256, 2)
void f16s_gemm(const __half* __restrict__ Ahi, const __half* __restrict__ Alo,
               const __half* __restrict__ Bhi, const __half* __restrict__ Blo,
               float* __restrict__ Cout,
               int No, int Ktot, int kspan, size_t zstride,
               const float* __restrict__ rowAdd, const float* __restrict__ colAdd,
               __half* __restrict__ Uhi, float* __restrict__ dotp)
{
    extern __shared__ __align__(128) unsigned char smem[];
    const uint32_t sbase = smem_u32(smem);
    const uint32_t OFF_AHI = 0, OFF_BHI = TILE_BYTES, OFF_BLO = 2 * TILE_BYTES;

    const int tid = threadIdx.x;
    const int wid = tid >> 5;
    const int lane = tid & 31;
    const int warp_m = wid >> 2;     // 0..1 -> 64 rows each
    const int warp_n = wid & 3;      // 0..3 -> 32 cols each
    const int rowA0 = blockIdx.y * 128;
    const int rowB0 = blockIdx.x * 128;
    const int kz = blockIdx.z * kspan;
    const int nslabs = kspan / 32;
    if (MODE == 0) Cout += (size_t)blockIdx.z * zstride;

    float acc[4][4][4];
#pragma unroll
    for (int i = 0; i < 4; i++)
#pragma unroll
        for (int j = 0; j < 4; j++)
#pragma unroll
            for (int v = 0; v < 4; v++) acc[i][j][v] = 0.0f;

    // ldmatrix lane addressing (k-invariant parts)
    const int a_row = warp_m * 64 + (lane & 15);
    const uint32_t a_coff = (uint32_t)((lane >> 4) << 4);
    const int b_row = warp_n * 32 + ((lane >> 4) << 3) + (lane & 7);
    const uint32_t b_coff = (uint32_t)(((lane >> 3) & 1) << 4);

    auto load_slab = [&](int slab, int stage) {
        const int kbase = kz + slab * 32;
        const uint32_t st = (uint32_t)stage * STAGE_BYTES;
#pragma unroll
        for (int i = 0; i < 2; i++) {
            const int idx = tid + i * 256;       // 0..511
            const int r = idx >> 2;
            const int c = idx & 3;
            const size_t aoff = (size_t)(rowA0 + r) * Ktot + kbase + c * 8;
            const size_t boff = (size_t)(rowB0 + r) * Ktot + kbase + c * 8;
            const uint32_t so = st + swz((uint32_t)r, (uint32_t)(c * 16));
            CP_ASYNC16(sbase + OFF_AHI + so, Ahi + aoff);
            CP_ASYNC16(sbase + OFF_BHI + so, Bhi + boff);
            CP_ASYNC16(sbase + OFF_BLO + so, Blo + boff);
        }
    };

    // 4-stage pipeline: prefetch distance 3.
    load_slab(0, 0); CP_COMMIT();
    if (nslabs > 1) { load_slab(1, 1); CP_COMMIT(); }
    if (nslabs > 2) { load_slab(2, 2); CP_COMMIT(); }

    for (int slab = 0; slab < nslabs; slab++) {
        // wait until slab's stage is complete (allow still-inflight prefetches)
        if (slab + 2 <= nslabs - 1)      { CP_WAIT2(); }
        else if (slab + 1 <= nslabs - 1) { CP_WAIT1(); }
        else                              { CP_WAIT0(); }
        __syncthreads();          // all warps done with slab-1 compute; stage free
        if (slab + 3 < nslabs) {
            load_slab(slab + 3, (slab + 3) & 3);
            CP_COMMIT();
        }

        const uint32_t st = (uint32_t)(slab & 3) * STAGE_BYTES;
#pragma unroll
        for (int kk = 0; kk < 2; kk++) {         // two k16 steps per slab
            const uint32_t kcol = kk * 32;
            uint32_t a_hi[4][4], b_hi[2][4], b_lo[2][4];
#pragma unroll
            for (int mi = 0; mi < 4; mi++) {
                const uint32_t row = (uint32_t)(a_row + mi * 16);
                const uint32_t ar = st + swz(row, kcol + a_coff);
                ldm_x4(a_hi[mi], sbase + OFF_AHI + ar);
            }
#pragma unroll
            for (int p = 0; p < 2; p++) {        // nj pairs {0,1}, {2,3}
                const uint32_t row = (uint32_t)(b_row + p * 16);
                const uint32_t br = st + swz(row, kcol + b_coff);
                ldm_x4(b_hi[p], sbase + OFF_BHI + br);
                ldm_x4(b_lo[p], sbase + OFF_BLO + br);
            }
#pragma unroll
            for (int prod = 0; prod < 2; prod++) {
#pragma unroll
                for (int mi = 0; mi < 4; mi++)
#pragma unroll
                    for (int nj = 0; nj < 4; nj++) {
                        const uint32_t* bv = (prod == 1) ? &b_lo[nj >> 1][(nj & 1) * 2]
                                                         : &b_hi[nj >> 1][(nj & 1) * 2];
                        mma_f16(acc[mi][nj], a_hi[mi], bv);
                    }
            }
        }
    }

    // ---------------- epilogue ----------------
    // c-frag layout: c0,c1 -> row lane/4, cols (lane%4)*2+{0,1}; c2,c3 -> row+8
    const int er0 = rowA0 + warp_m * 64 + (lane >> 2);
    const int ec0 = rowB0 + warp_n * 32 + (lane & 3) * 2;

    if (MODE == 2) {
        __syncthreads();                          // mainloop smem reuse
        float* sm_dot = (float*)smem;             // [128 rows][4 warp_n]
#pragma unroll
        for (int mi = 0; mi < 4; mi++) {
#pragma unroll
            for (int half = 0; half < 2; half++) {
                const int row = er0 + mi * 16 + half * 8;
                float rs = 0.0f;
#pragma unroll
                for (int nj = 0; nj < 4; nj++) {
                    const int col = ec0 + nj * 8;
                    float2 v;
                    v.x = acc[mi][nj][half * 2 + 0];
                    v.y = acc[mi][nj][half * 2 + 1];
                    // A value at (row, col) in fp32 (hi+lo)
                    const size_t o = (size_t)row * Ktot + col;
                    const float ax = __half2float(Ahi[o])     + __half2float(Alo[o]);
                    const float ay = __half2float(Ahi[o + 1]) + __half2float(Alo[o + 1]);
                    rs = fmaf(ax, v.x, rs);
                    rs = fmaf(ay, v.y, rs);
                    if (row < DIM_K) {            // write U (fp16 hi only)
                        __half2 h2;
                        h2.x = __float2half_rn(v.x);
                        h2.y = __float2half_rn(v.y);
                        *(__half2*)(Uhi + (size_t)row * DIM_D + col) = h2;
                    }
                }
                rs += __shfl_xor_sync(0xFFFFFFFFu, rs, 1);
                rs += __shfl_xor_sync(0xFFFFFFFFu, rs, 2);
                if ((lane & 3) == 0) {
                    const int lr = warp_m * 64 + mi * 16 + half * 8 + (lane >> 2);
                    sm_dot[lr * 4 + warp_n] = rs;
                }
            }
        }
        __syncthreads();
        if (tid < 128) {
            const float s = sm_dot[tid * 4] + sm_dot[tid * 4 + 1]
                          + sm_dot[tid * 4 + 2] + sm_dot[tid * 4 + 3];
            dotp[(size_t)blockIdx.x * DIM_CM + rowA0 + tid] = s;
        }
        return;
    }

#pragma unroll
    for (int mi = 0; mi < 4; mi++) {
#pragma unroll
        for (int half = 0; half < 2; half++) {
            const int row = er0 + mi * 16 + half * 8;
            float radd = 0.0f;
            if (MODE == 1) radd = rowAdd[row];
#pragma unroll
            for (int nj = 0; nj < 4; nj++) {
                const int col = ec0 + nj * 8;
                float2 v;
                v.x = acc[mi][nj][half * 2 + 0];
                v.y = acc[mi][nj][half * 2 + 1];
                if (MODE == 1) {
                    const float2 ca = *(const float2*)(colAdd + col);
                    v.x = sqrtf(fmaxf(ca.x - 2.0f * v.x + radd, 0.0f));
                    v.y = sqrtf(fmaxf(ca.y - 2.0f * v.y + radd, 0.0f));
                }
                *(float2*)(Cout + (size_t)row * No + col) = v;
            }
        }
    }
}

// ------------------------- conversion / small kernels -----------------------
__global__ void split_kernel(const float* __restrict__ in,
                             __half* __restrict__ hi,
                             __half* __restrict__ lo, int n)
{
    const int i = blockIdx.x * blockDim.x + threadIdx.x;
    if (i >= n) return;
    const float x = in[i];
    const __half h = __float2half_rn(x);
    hi[i] = h;
    lo[i] = __float2half_rn(x - __half2float(h));
}

// in [R,C] fp32 -> hi/lo [C,R] fp16 (transpose)
__global__ void split_transpose_kernel(const float* __restrict__ in,
                                       __half* __restrict__ hi,
                                       __half* __restrict__ lo, int R, int C)
{
    __shared__ float t[32][33];
    const int x = blockIdx.x * 32 + threadIdx.x;  // col in input
    const int y0 = blockIdx.y * 32;
#pragma unroll
    for (int j = 0; j < 32; j += 8)
        t[threadIdx.y + j][threadIdx.x] = in[(size_t)(y0 + threadIdx.y + j) * C + x];
    __syncthreads();
#pragma unroll
    for (int j = 0; j < 32; j += 8) {
        const int c = blockIdx.x * 32 + threadIdx.y + j;  // out row (= input col)
        const int r = y0 + threadIdx.x;                   // out col (= input row)
        const float v = t[threadIdx.x][threadIdx.y + j];
        const __half h = __float2half_rn(v);
        hi[(size_t)c * R + r] = h;
        lo[(size_t)c * R + r] = __float2half_rn(v - __half2float(h));
    }
}

// sum split-K partials of S and split to fp16 hi/lo in one pass
__global__ void reduce_split_kernel(const float* __restrict__ part,
                                    __half* __restrict__ hi,
                                    __half* __restrict__ lo, int n)
{
    const int i = blockIdx.x * blockDim.x + threadIdx.x;
    if (i >= n) return;
    float acc = 0.0f;
#pragma unroll
    for (int z = 0; z < ZSPLIT; z++) acc += part[i + (size_t)z * n];
    const __half h = __float2half_rn(acc);
    hi[i] = h;
    lo[i] = __float2half_rn(acc - __half2float(h));
}

// xc2/xm2 = sum of 4 col-band partials
__global__ void combine_dots_kernel(const float* __restrict__ dotp,
                                    float* __restrict__ xc2, float* __restrict__ xm2)
{
    const int i = blockIdx.x * blockDim.x + threadIdx.x;
    if (i >= DIM_CM) return;
    const float s = dotp[i] + dotp[DIM_CM + i] + dotp[2 * DIM_CM + i] + dotp[3 * DIM_CM + i];
    if (i < DIM_K) xc2[i] = s;
    else           xm2[i - DIM_K] = s;
}

// --------------------------------- launch ----------------------------------
extern "C" void kernel_launch(void* const* d_in, const int* in_sizes, int n_in,
                              void* d_out, int out_size)
{
    const float* X = (const float*)d_in[0];  // [4096, 512]
    const float* M = (const float*)d_in[1];  // [512, 4096]
    const float* C = (const float*)d_in[2];  // [2048, 512]
    float* out = (float*)d_out;              // [2048, 4096]

    static bool attr_done = false;
    if (!attr_done) {
        cudaFuncSetAttribute(f16s_gemm<0>, cudaFuncAttributeMaxDynamicSharedMemorySize, GEMM_SMEM);
        cudaFuncSetAttribute(f16s_gemm<1>, cudaFuncAttributeMaxDynamicSharedMemorySize, GEMM_SMEM);
        cudaFuncSetAttribute(f16s_gemm<2>, cudaFuncAttributeMaxDynamicSharedMemorySize, GEMM_SMEM);
        attr_done = true;
    }

    __half *Xt_hi, *Xt_lo, *CM_hi, *CM_lo, *S_hi, *S_lo, *U_hi;
    float *Spart, *dotp, *xm2, *xc2;
    cudaGetSymbolAddress((void**)&Xt_hi, g_Xt_hi);
    cudaGetSymbolAddress((void**)&Xt_lo, g_Xt_lo);
    cudaGetSymbolAddress((void**)&CM_hi, g_CM_hi);
    cudaGetSymbolAddress((void**)&CM_lo, g_CM_lo);
    cudaGetSymbolAddress((void**)&S_hi,  g_S_hi);
    cudaGetSymbolAddress((void**)&S_lo,  g_S_lo);
    cudaGetSymbolAddress((void**)&U_hi,  g_U_hi);
    cudaGetSymbolAddress((void**)&Spart, g_Spart);
    cudaGetSymbolAddress((void**)&dotp,  g_dotp);
    cudaGetSymbolAddress((void**)&xm2,   g_xm2);
    cudaGetSymbolAddress((void**)&xc2,   g_xc2);

    __half* Mt_hi = CM_hi + (size_t)DIM_K * DIM_D;  // rows 2048..6143
    __half* Mt_lo = CM_lo + (size_t)DIM_K * DIM_D;

    // 1) transposed splits: Xt [512,4096]; stacked CM = [C; M^T] [6144,512]
    split_transpose_kernel<<<dim3(DIM_D / 32, DIM_N / 32), dim3(32, 8)>>>(X, Xt_hi, Xt_lo, DIM_N, DIM_D);
    split_kernel<<<(DIM_K * DIM_D) / 256, 256>>>(C, CM_hi, CM_lo, DIM_K * DIM_D);
    split_transpose_kernel<<<dim3(DIM_M / 32, DIM_D / 32), dim3(32, 8)>>>(M, Mt_hi, Mt_lo, DIM_D, DIM_M);

    // 2) S = Xt_hi @ (Xt_hi+Xt_lo)^T  [512,512], K=4096, split-K=16
    f16s_gemm<0><<<dim3(DIM_D / 128, DIM_D / 128, ZSPLIT), 256, GEMM_SMEM>>>(
        Xt_hi, nullptr, Xt_hi, Xt_lo, Spart,
        DIM_D, DIM_N, DIM_N / ZSPLIT, (size_t)DIM_D * DIM_D,
        nullptr, nullptr, nullptr, nullptr);
    reduce_split_kernel<<<(DIM_D * DIM_D) / 256, 256>>>(Spart, S_hi, S_lo, DIM_D * DIM_D);

    // 3) UT = CM_hi @ (S_hi+S_lo)  (MODE2: writes U_hi for C rows + dot partials)
    f16s_gemm<2><<<dim3(DIM_D / 128, DIM_CM / 128, 1), 256, GEMM_SMEM>>>(
        CM_hi, CM_lo, S_hi, S_lo, nullptr, DIM_D, DIM_D, DIM_D, 0,
        nullptr, nullptr, U_hi, dotp);

    // 4) xc2[k] = c_k^T S c_k ; xm2[m] = m^T S m
    combine_dots_kernel<<<(DIM_CM + 255) / 256, 256>>>(dotp, xc2, xm2);

    // 5) out[k,m] = sqrt(max(xm2[m] - 2*(U_hi @ (Mt_hi+Mt_lo)^T)[k,m] + xc2[k], 0))
    f16s_gemm<1><<<dim3(DIM_M / 128, DIM_K / 128, 1), 256, GEMM_SMEM>>>(
        U_hi, nullptr, Mt_hi, Mt_lo, out, DIM_M, DIM_D, DIM_D, 0,
        xc2, xm2, nullptr, nullptr);
}